// round 16
// baseline (speedup 1.0000x reference)
#include <cuda_runtime.h>
#include <cuda_bf16.h>
#include <math.h>

#define Bb 2
#define SS 1024
#define MM 1024
#define DD 1024
#define HH 16
#define DH 64
#define FF 2048
#define KP (DD/2)

// ---------------- scratch (device globals; no allocation allowed) ----------------
__device__ float g_xt[(size_t)Bb*FF*DD];
__device__ float g_q [(size_t)Bb*SS*DD];
__device__ float g_k [(size_t)Bb*FF*DD];
__device__ float g_v [(size_t)Bb*FF*DD];
__device__ float g_rel[(size_t)FF*DD];
__device__ float g_Qr[(size_t)FF*DD];
__device__ float g_bd[(size_t)Bb*HH*SS*FF];
__device__ float g_sc[(size_t)Bb*HH*SS*FF];
__device__ float g_sg[(size_t)Bb*SS*DD];
__device__ float g_g1[(size_t)Bb*SS*DD];
__device__ float g_tu[(size_t)Bb*HH*FF];
__device__ float g_tv[(size_t)HH*FF];
__device__ float g_wr[(size_t)4*DD*DD];
__device__ unsigned g_wtb[(size_t)5*DD*KP];
__device__ unsigned g_abf[(size_t)Bb*HH*SS*(FF/2)];
__device__ unsigned g_vt[(size_t)Bb*HH*DH*(FF/2)];
__device__ unsigned g_aob[(size_t)Bb*SS*KP];
__device__ unsigned g_ibf[(size_t)Bb*SS*KP];
__device__ unsigned g_g1b[(size_t)Bb*SS*KP];
__device__ unsigned g_h0b[(size_t)Bb*SS*KP];
__device__ unsigned g_h1b[(size_t)Bb*SS*KP];
__device__ float g_bhmax[Bb*HH];

// ---------------- helpers ----------------
__device__ __forceinline__ float gelu_exact(float x) {
    return 0.5f * x * (1.0f + erff(x * 0.70710678118654752440f));
}
__device__ __forceinline__ float fexp(float x) {
    float y = x * 1.4426950408889634f;
    y = fminf(fmaxf(y, -126.0f), 126.0f);
    float n = rintf(y);
    float f = y - n;
    float p = 1.54035304e-4f;
    p = fmaf(p, f, 1.33335581e-3f);
    p = fmaf(p, f, 9.61812911e-3f);
    p = fmaf(p, f, 5.55041087e-2f);
    p = fmaf(p, f, 2.40226512e-1f);
    p = fmaf(p, f, 6.93147182e-1f);
    p = fmaf(p, f, 1.0f);
    return __int_as_float(((int)n + 127) << 23) * p;
}
__device__ __forceinline__ float sigmoidf(float x) {
    return 1.0f / (1.0f + fexp(-x));
}
__device__ __forceinline__ unsigned rna(unsigned x) {
    unsigned u;
    asm("cvt.rna.tf32.f32 %0, %1;" : "=r"(u) : "f"(__uint_as_float(x)));
    return u;
}
__device__ __forceinline__ float rnaf(float x) {
    unsigned u;
    asm("cvt.rna.tf32.f32 %0, %1;" : "=r"(u) : "f"(x));
    return __uint_as_float(u);
}
__device__ __forceinline__ void mma8(float* c, const unsigned* a, const unsigned* b) {
    asm volatile("mma.sync.aligned.m16n8k8.row.col.f32.tf32.tf32.f32 "
        "{%0,%1,%2,%3}, {%4,%5,%6,%7}, {%8,%9}, {%0,%1,%2,%3};"
        : "+f"(c[0]), "+f"(c[1]), "+f"(c[2]), "+f"(c[3])
        : "r"(a[0]), "r"(a[1]), "r"(a[2]), "r"(a[3]), "r"(b[0]), "r"(b[1]));
}
__device__ __forceinline__ void mma16(float* c, const unsigned* a, const unsigned* b) {
    asm volatile("mma.sync.aligned.m16n8k16.row.col.f32.bf16.bf16.f32 "
        "{%0,%1,%2,%3}, {%4,%5,%6,%7}, {%8,%9}, {%0,%1,%2,%3};"
        : "+f"(c[0]), "+f"(c[1]), "+f"(c[2]), "+f"(c[3])
        : "r"(a[0]), "r"(a[1]), "r"(a[2]), "r"(a[3]), "r"(b[0]), "r"(b[1]));
}
__device__ __forceinline__ void cpa16(void* smem, const void* gmem) {
    unsigned s = (unsigned)__cvta_generic_to_shared(smem);
    asm volatile("cp.async.ca.shared.global [%0], [%1], 16;" :: "r"(s), "l"(gmem));
}
__device__ __forceinline__ void cpa_commit() { asm volatile("cp.async.commit_group;"); }
template<int N_> __device__ __forceinline__ void cpa_wait() {
    asm volatile("cp.async.wait_group %0;" :: "n"(N_));
}
__device__ __forceinline__ unsigned packbf(float a, float b) {
    __nv_bfloat162 h = __floats2bfloat162_rn(a, b);
    return *(unsigned*)&h;
}

// ---------------- pre-round 4 attention weights (tf32 values) ----------------
struct Ptr4 { const float* p[4]; };
__global__ __launch_bounds__(256) void wround4_k(Ptr4 srcs, float* __restrict__ d)
{
    int m = blockIdx.y;
    int i = blockIdx.x * 256 + threadIdx.x;
    const float4* s = (const float4*)srcs.p[m];
    float4 v = s[i];
    v.x = rnaf(v.x); v.y = rnaf(v.y); v.z = rnaf(v.z); v.w = rnaf(v.w);
    ((float4*)(d + (size_t)m * DD * DD))[i] = v;
}

// ---------------- transpose+pack 5 FFN weights to bf16 Wt[n][k/2] ----------------
struct Ptr5 { const float* p[5]; };
__global__ __launch_bounds__(256) void wtrans5_k(Ptr5 srcs, unsigned* __restrict__ d)
{
    int m = blockIdx.y;
    int tile = blockIdx.x;
    int kt = tile >> 3, nt = tile & 7;
    int k0 = kt * 64, n0 = nt * 128;
    __shared__ float vs[64][129];
    const float* W = srcs.p[m];
    int t = threadIdx.x;
    #pragma unroll
    for (int j = 0; j < 8; j++) {
        int idx = t + j * 256;
        int kr = idx >> 5, nc4 = (idx & 31) * 4;
        float4 x = *(const float4*)(W + (size_t)(k0 + kr) * DD + n0 + nc4);
        vs[kr][nc4] = x.x; vs[kr][nc4 + 1] = x.y; vs[kr][nc4 + 2] = x.z; vs[kr][nc4 + 3] = x.w;
    }
    __syncthreads();
    unsigned* dst = d + (size_t)m * DD * KP;
    #pragma unroll
    for (int j = 0; j < 16; j++) {
        int idx = t + j * 256;
        int n = idx >> 5, kp = idx & 31;
        dst[(size_t)(n0 + n) * KP + k0 / 2 + kp] = packbf(vs[2 * kp][n], vs[2 * kp + 1][n]);
    }
}

// ---------------- fp32 -> packed bf16 ----------------
__global__ __launch_bounds__(256) void tobf_k(
    const float2* __restrict__ s, unsigned* __restrict__ d, int n)
{
    int i = blockIdx.x * 256 + threadIdx.x;
    if (i < n) { float2 v = s[i]; d[i] = packbf(v.x, v.y); }
}

// ---------------- pick rel_enc among two same-sized candidates ----------------
__global__ __launch_bounds__(256) void pick_rel_k(
    const float* __restrict__ c2, const float* __restrict__ c3, float* __restrict__ dst)
{
    __shared__ int isrel2;
    if (threadIdx.x == 0) {
        int r = 0;
        #pragma unroll
        for (int i = 0; i < 64; i++) {
            float v = c2[i];
            if (v != 0.0f && v != 1.0f) { r = 1; break; }
        }
        isrel2 = r;
    }
    __syncthreads();
    const float4* src = (const float4*)(isrel2 ? c2 : c3);
    int i = blockIdx.x * 256 + threadIdx.x;
    const int n4 = (FF * DD) / 4;
    if (i < n4) {
        float4 v = src[i];
        v.x = rnaf(v.x); v.y = rnaf(v.y); v.z = rnaf(v.z); v.w = rnaf(v.w);
        ((float4*)dst)[i] = v;
    }
}

// ---------------- layernorms ----------------
__global__ __launch_bounds__(256) void ln_concat_k(
    const float* __restrict__ inp, const float* __restrict__ mem,
    const float* __restrict__ g, const float* __restrict__ b,
    float* __restrict__ out)
{
    int row = blockIdx.x;
    int bb = row / FF; int fr = row - bb * FF;
    const float* src = (fr < MM) ? (mem + ((size_t)bb*MM + fr) * DD)
                                 : (inp + ((size_t)bb*SS + (fr - MM)) * DD);
    float* dst = out + (size_t)row * DD;
    int t = threadIdx.x;
    float4 x = ((const float4*)src)[t];
    float s  = x.x + x.y + x.z + x.w;
    float q  = x.x*x.x + x.y*x.y + x.z*x.z + x.w*x.w;
    #pragma unroll
    for (int o = 16; o; o >>= 1) {
        s += __shfl_xor_sync(0xffffffffu, s, o);
        q += __shfl_xor_sync(0xffffffffu, q, o);
    }
    __shared__ float rs[8], rq[8];
    int w = t >> 5, l = t & 31;
    if (l == 0) { rs[w] = s; rq[w] = q; }
    __syncthreads();
    float st = 0.f, qt = 0.f;
    #pragma unroll
    for (int i = 0; i < 8; i++) { st += rs[i]; qt += rq[i]; }
    float mean = st * (1.0f / DD);
    float var  = qt * (1.0f / DD) - mean * mean;
    float r = rsqrtf(var + 1e-5f);
    float4 gg = ((const float4*)g)[t];
    float4 bv = ((const float4*)b)[t];
    float4 y;
    y.x = rnaf((x.x - mean) * r * gg.x + bv.x);
    y.y = rnaf((x.y - mean) * r * gg.y + bv.y);
    y.z = rnaf((x.z - mean) * r * gg.z + bv.z);
    y.w = rnaf((x.w - mean) * r * gg.w + bv.w);
    ((float4*)dst)[t] = y;
}

__global__ __launch_bounds__(256) void ln_bf_k(
    const float* __restrict__ a,
    const float* __restrict__ g, const float* __restrict__ b,
    unsigned* __restrict__ outb)
{
    int row = blockIdx.x;
    const float* src = a + (size_t)row * DD;
    int t = threadIdx.x;
    float4 x = ((const float4*)src)[t];
    float s  = x.x + x.y + x.z + x.w;
    float q  = x.x*x.x + x.y*x.y + x.z*x.z + x.w*x.w;
    #pragma unroll
    for (int o = 16; o; o >>= 1) {
        s += __shfl_xor_sync(0xffffffffu, s, o);
        q += __shfl_xor_sync(0xffffffffu, q, o);
    }
    __shared__ float rs[8], rq[8];
    int w = t >> 5, l = t & 31;
    if (l == 0) { rs[w] = s; rq[w] = q; }
    __syncthreads();
    float st = 0.f, qt = 0.f;
    #pragma unroll
    for (int i = 0; i < 8; i++) { st += rs[i]; qt += rq[i]; }
    float mean = st * (1.0f / DD);
    float var  = qt * (1.0f / DD) - mean * mean;
    float r = rsqrtf(var + 1e-5f);
    float4 gg = ((const float4*)g)[t];
    float4 bv = ((const float4*)b)[t];
    float y0 = (x.x - mean) * r * gg.x + bv.x;
    float y1 = (x.y - mean) * r * gg.y + bv.y;
    float y2 = (x.z - mean) * r * gg.z + bv.z;
    float y3 = (x.w - mean) * r * gg.w + bv.w;
    ((uint2*)(outb + (size_t)row * KP))[t] = make_uint2(packbf(y0, y1), packbf(y2, y3));
}

// ---------------- rank-1 terms ----------------
__global__ __launch_bounds__(256) void pdot_k(
    const float* __restrict__ par, const float* __restrict__ mat,
    long zStride, int useB, float* __restrict__ outp)
{
    int z = blockIdx.y;
    int h = useB ? (z & 15) : z;
    long base = useB ? (long)(z >> 4) * zStride : 0;
    int f = blockIdx.x * 8 + (threadIdx.x >> 5);
    int lane = threadIdx.x & 31;
    float2 pv = *(const float2*)(par + h * DH + lane * 2);
    float2 mv = *(const float2*)(mat + base + (size_t)f * DD + h * DH + lane * 2);
    float s = pv.x * mv.x + pv.y * mv.y;
    #pragma unroll
    for (int o = 16; o; o >>= 1) s += __shfl_xor_sync(0xffffffffu, s, o);
    if (lane == 0) outp[(size_t)z * FF + f] = s;
}

// ================= fused tf32 GEMM: q,k,v,Qr (256 thr, 4-stage cp.async) =================
#define GST 3
#define GT  4
#define GEMM_SMEM (GT * (128*20 + 16*136) * 4)
struct T4 {
    const float* xt; const float* rel;
    const float* wq; const float* wke; const float* wv; const float* wkr;
    float* q; float* k; float* v; float* Qr;
};
__global__ __launch_bounds__(256, 2) void gemm_t4(T4 p)
{
    extern __shared__ unsigned sh[];
    unsigned (*As)[128][20] = (unsigned(*)[128][20])sh;
    unsigned (*Ws)[16][136] = (unsigned(*)[16][136])(sh + GT * 128 * 20);
    const int y = blockIdx.y;
    const float* A; const float* W; float* C; int cr;
    if (y < 16) {
        int b = y >> 3, rt = y & 7;
        A = p.xt + (size_t)b * FF * DD + (size_t)MM * DD + (size_t)rt * 128 * DD;
        C = p.q  + (size_t)b * SS * DD + (size_t)rt * 128 * DD;
        W = p.wq; cr = 1;
    } else if (y < 48) {
        int rt = y - 16;
        A = p.xt + (size_t)rt * 128 * DD;
        C = p.k  + (size_t)rt * 128 * DD;
        W = p.wke; cr = 0;
    } else if (y < 80) {
        int rt = y - 48;
        A = p.xt + (size_t)rt * 128 * DD;
        C = p.v  + (size_t)rt * 128 * DD;
        W = p.wv; cr = 1;
    } else {
        int rt = y - 80;
        A = p.rel + (size_t)rt * 128 * DD;
        C = p.Qr  + (size_t)rt * 128 * DD;
        W = p.wkr; cr = 0;
    }
    const int bn = blockIdx.x * 128;
    const int t = threadIdx.x, lane = t & 31, wid = t >> 5;
    const int wm = wid >> 2, wn = wid & 3;
    const int g = lane >> 2, tg = lane & 3;
    const int am = t >> 2, ak = (t & 3) * 4;
    const float* Ap0 = A + (size_t)am * DD + ak;
    const float* Ap1 = Ap0 + (size_t)64 * DD;
    const int wk = t >> 5, wnc = (t & 31) * 4;
    const float* Wp0 = W + (size_t)wk * DD + bn + wnc;
    const float* Wp1 = Wp0 + (size_t)8 * DD;

    float acc[4][4][4];
    #pragma unroll
    for (int i = 0; i < 4; i++)
        #pragma unroll
        for (int j = 0; j < 4; j++)
            #pragma unroll
            for (int r = 0; r < 4; r++) acc[i][j][r] = 0.f;

    const int NIT = DD >> 4;
    #pragma unroll 1
    for (int s = 0; s < GT - 1; s++) {
        long o = (long)s * 16;
        cpa16(&As[s][am][ak],      Ap0 + o);
        cpa16(&As[s][am + 64][ak], Ap1 + o);
        cpa16(&Ws[s][wk][wnc],     Wp0 + o * DD);
        cpa16(&Ws[s][wk + 8][wnc], Wp1 + o * DD);
        cpa_commit();
    }

    for (int it = 0; it < NIT; ++it) {
        cpa_wait<GT - 2>();
        __syncthreads();
        if (it + GT - 1 < NIT) {
            int st = (it + GT - 1) % GT;
            long o = (long)(it + GT - 1) * 16;
            cpa16(&As[st][am][ak],      Ap0 + o);
            cpa16(&As[st][am + 64][ak], Ap1 + o);
            cpa16(&Ws[st][wk][wnc],     Wp0 + o * DD);
            cpa16(&Ws[st][wk + 8][wnc], Wp1 + o * DD);
            cpa_commit();
        }
        const int cur = it % GT;
        #pragma unroll
        for (int kk = 0; kk < 16; kk += 8) {
            unsigned af[4][4], bf[4][2];
            #pragma unroll
            for (int mt = 0; mt < 4; mt++) {
                int r = wm * 64 + mt * 16 + g;
                af[mt][0] = As[cur][r][kk + tg];
                af[mt][1] = As[cur][r + 8][kk + tg];
                af[mt][2] = As[cur][r][kk + tg + 4];
                af[mt][3] = As[cur][r + 8][kk + tg + 4];
            }
            #pragma unroll
            for (int nt = 0; nt < 4; nt++) {
                int c = wn * 32 + nt * 8 + g;
                bf[nt][0] = Ws[cur][kk + tg][c];
                bf[nt][1] = Ws[cur][kk + tg + 4][c];
            }
            #pragma unroll
            for (int mt = 0; mt < 4; mt++)
                #pragma unroll
                for (int nt = 0; nt < 4; nt++)
                    mma8(acc[mt][nt], af[mt], bf[nt]);
        }
    }

    #pragma unroll
    for (int mt = 0; mt < 4; mt++) {
        int gm = wm * 64 + mt * 16 + g;
        #pragma unroll
        for (int nt = 0; nt < 4; nt++) {
            int gn = bn + wn * 32 + nt * 8 + tg * 2;
            float x0 = acc[mt][nt][0], x1 = acc[mt][nt][1];
            float x2 = acc[mt][nt][2], x3 = acc[mt][nt][3];
            if (cr) { x0 = rnaf(x0); x1 = rnaf(x1); x2 = rnaf(x2); x3 = rnaf(x3); }
            *(float2*)&C[(size_t)gm * DD + gn]       = make_float2(x0, x1);
            *(float2*)&C[(size_t)(gm + 8) * DD + gn] = make_float2(x2, x3);
        }
    }
}

// ================= bf16 FFN GEMM with fused epilogues (4-stage) =================
// EPI 0: out1 = sigmoid(acc + bias)                          (gate1 -> sg)
// EPI 1: g = e1 + e2 * gelu(acc); out1 = g fp32, out2 = g bf16  (wf + gate-apply)
// EPI 2: out1 = e1 + e2 * gelu(acc + bias)                   (w2 + final gate)
#define GB_SMEM (GT * 128 * 20 * 2 * 4)
template<int EPI>
__global__ __launch_bounds__(256, 2) void gemm_bf(
    const unsigned* __restrict__ A, const unsigned* __restrict__ Wt,
    const float* __restrict__ bias,
    const float* __restrict__ e1, const float* __restrict__ e2,
    float* __restrict__ out1, unsigned* __restrict__ out2)
{
    extern __shared__ unsigned sh[];
    unsigned (*As)[128][20] = (unsigned(*)[128][20])sh;
    unsigned (*Ws)[128][20] = (unsigned(*)[128][20])(sh + GT * 128 * 20);
    const int bm = blockIdx.y * 128, bn = blockIdx.x * 128;
    const int t = threadIdx.x, lane = t & 31, wid = t >> 5;
    const int wm = wid >> 2, wn = wid & 3;
    const int g = lane >> 2, tg = lane & 3;
    const int ar = t >> 1, ac = (t & 1) * 8;
    const unsigned* Ap = A  + (size_t)(bm + ar) * KP + ac;
    const unsigned* Wp = Wt + (size_t)(bn + ar) * KP + ac;

    float acc[4][4][4];
    #pragma unroll
    for (int i = 0; i < 4; i++)
        #pragma unroll
        for (int j = 0; j < 4; j++)
            #pragma unroll
            for (int r = 0; r < 4; r++) acc[i][j][r] = 0.f;

    const int NIT = KP / 16;
    #pragma unroll 1
    for (int s = 0; s < GT - 1; s++) {
        long o = (long)s * 16;
        cpa16(&As[s][ar][ac],     Ap + o);
        cpa16(&As[s][ar][ac + 4], Ap + o + 4);
        cpa16(&Ws[s][ar][ac],     Wp + o);
        cpa16(&Ws[s][ar][ac + 4], Wp + o + 4);
        cpa_commit();
    }

    for (int it = 0; it < NIT; ++it) {
        cpa_wait<GT - 2>();
        __syncthreads();
        if (it + GT - 1 < NIT) {
            int st = (it + GT - 1) % GT;
            long o = (long)(it + GT - 1) * 16;
            cpa16(&As[st][ar][ac],     Ap + o);
            cpa16(&As[st][ar][ac + 4], Ap + o + 4);
            cpa16(&Ws[st][ar][ac],     Wp + o);
            cpa16(&Ws[st][ar][ac + 4], Wp + o + 4);
            cpa_commit();
        }
        const int cur = it % GT;
        #pragma unroll
        for (int kkp = 0; kkp < 16; kkp += 8) {
            unsigned af[4][4], bf[4][2];
            #pragma unroll
            for (int mt = 0; mt < 4; mt++) {
                int r = wm * 64 + mt * 16 + g;
                af[mt][0] = As[cur][r][kkp + tg];
                af[mt][1] = As[cur][r + 8][kkp + tg];
                af[mt][2] = As[cur][r][kkp + tg + 4];
                af[mt][3] = As[cur][r + 8][kkp + tg + 4];
            }
            #pragma unroll
            for (int nt = 0; nt < 4; nt++) {
                int c = wn * 32 + nt * 8 + g;
                bf[nt][0] = Ws[cur][c][kkp + tg];
                bf[nt][1] = Ws[cur][c][kkp + tg + 4];
            }
            #pragma unroll
            for (int mt = 0; mt < 4; mt++)
                #pragma unroll
                for (int nt = 0; nt < 4; nt++)
                    mma16(acc[mt][nt], af[mt], bf[nt]);
        }
    }

    #pragma unroll
    for (int mt = 0; mt < 4; mt++) {
        int gm = bm + wm * 64 + mt * 16 + g;
        #pragma unroll
        for (int nt = 0; nt < 4; nt++) {
            int gn = bn + wn * 32 + nt * 8 + tg * 2;
            float b0v = bias ? bias[gn]     : 0.f;
            float b1v = bias ? bias[gn + 1] : 0.f;
            #pragma unroll
            for (int half = 0; half < 2; half++) {
                int gmr = gm + half * 8;
                float x0 = acc[mt][nt][half * 2 + 0] + b0v;
                float x1 = acc[mt][nt][half * 2 + 1] + b1v;
                if (EPI == 0) {
                    x0 = sigmoidf(x0); x1 = sigmoidf(x1);
                    *(float2*)&out1[(size_t)gmr * DD + gn] = make_float2(x0, x1);
                } else if (EPI == 1) {
                    x0 = gelu_exact(x0); x1 = gelu_exact(x1);
                    float2 iv = *(const float2*)&e1[(size_t)gmr * DD + gn];
                    float2 sv = *(const float2*)&e2[(size_t)gmr * DD + gn];
                    float g0 = iv.x + sv.x * x0;
                    float g1v = iv.y + sv.y * x1;
                    *(float2*)&out1[(size_t)gmr * DD + gn] = make_float2(g0, g1v);
                    out2[(size_t)gmr * KP + (gn >> 1)] = packbf(g0, g1v);
                } else {
                    x0 = gelu_exact(x0); x1 = gelu_exact(x1);
                    float2 iv = *(const float2*)&e1[(size_t)gmr * DD + gn];
                    float2 sv = *(const float2*)&e2[(size_t)gmr * DD + gn];
                    *(float2*)&out1[(size_t)gmr * DD + gn] =
                        make_float2(iv.x + sv.x * x0, iv.y + sv.y * x1);
                }
            }
        }
    }
}

// ================= bf16 dual-segment GEMM (h1 + gate2), 4-stage =================
struct BSeg { const unsigned* A; const unsigned* Wt; const float* bias; void* C; int act; int cb; };
struct B2 { BSeg s0, s1; };
__global__ __launch_bounds__(256, 2) void gemm_b2(B2 p)
{
    extern __shared__ unsigned sh[];
    unsigned (*As)[128][20] = (unsigned(*)[128][20])sh;
    unsigned (*Ws)[128][20] = (unsigned(*)[128][20])(sh + GT * 128 * 20);
    const int y = blockIdx.y;
    BSeg sg = (y < 16) ? p.s0 : p.s1;
    const int rt = (y < 16) ? y : y - 16;
    const int bm = rt * 128, bn = blockIdx.x * 128;
    const int t = threadIdx.x, lane = t & 31, wid = t >> 5;
    const int wm = wid >> 2, wn = wid & 3;
    const int g = lane >> 2, tg = lane & 3;
    const int ar = t >> 1, ac = (t & 1) * 8;
    const unsigned* Ap = sg.A  + (size_t)(bm + ar) * KP + ac;
    const unsigned* Wp = sg.Wt + (size_t)(bn + ar) * KP + ac;

    float acc[4][4][4];
    #pragma unroll
    for (int i = 0; i < 4; i++)
        #pragma unroll
        for (int j = 0; j < 4; j++)
            #pragma unroll
            for (int r = 0; r < 4; r++) acc[i][j][r] = 0.f;

    const int NIT = KP / 16;
    #pragma unroll 1
    for (int s = 0; s < GT - 1; s++) {
        long o = (long)s * 16;
        cpa16(&As[s][ar][ac],     Ap + o);
        cpa16(&As[s][ar][ac + 4], Ap + o + 4);
        cpa16(&Ws[s][ar][ac],     Wp + o);
        cpa16(&Ws[s][ar][ac + 4], Wp + o + 4);
        cpa_commit();
    }

    for (int it = 0; it < NIT; ++it) {
        cpa_wait<GT - 2>();
        __syncthreads();
        if (it + GT - 1 < NIT) {
            int st = (it + GT - 1) % GT;
            long o = (long)(it + GT - 1) * 16;
            cpa16(&As[st][ar][ac],     Ap + o);
            cpa16(&As[st][ar][ac + 4], Ap + o + 4);
            cpa16(&Ws[st][ar][ac],     Wp + o);
            cpa16(&Ws[st][ar][ac + 4], Wp + o + 4);
            cpa_commit();
        }
        const int cur = it % GT;
        #pragma unroll
        for (int kkp = 0; kkp < 16; kkp += 8) {
            unsigned af[4][4], bf[4][2];
            #pragma unroll
            for (int mt = 0; mt < 4; mt++) {
                int r = wm * 64 + mt * 16 + g;
                af[mt][0] = As[cur][r][kkp + tg];
                af[mt][1] = As[cur][r + 8][kkp + tg];
                af[mt][2] = As[cur][r][kkp + tg + 4];
                af[mt][3] = As[cur][r + 8][kkp + tg + 4];
            }
            #pragma unroll
            for (int nt = 0; nt < 4; nt++) {
                int c = wn * 32 + nt * 8 + g;
                bf[nt][0] = Ws[cur][c][kkp + tg];
                bf[nt][1] = Ws[cur][c][kkp + tg + 4];
            }
            #pragma unroll
            for (int mt = 0; mt < 4; mt++)
                #pragma unroll
                for (int nt = 0; nt < 4; nt++)
                    mma16(acc[mt][nt], af[mt], bf[nt]);
        }
    }

    #pragma unroll
    for (int mt = 0; mt < 4; mt++) {
        int gm = bm + wm * 64 + mt * 16 + g;
        #pragma unroll
        for (int nt = 0; nt < 4; nt++) {
            int gn = bn + wn * 32 + nt * 8 + tg * 2;
            float b0v = sg.bias ? sg.bias[gn]     : 0.f;
            float b1v = sg.bias ? sg.bias[gn + 1] : 0.f;
            float x0 = acc[mt][nt][0] + b0v, x1 = acc[mt][nt][1] + b1v;
            float x2 = acc[mt][nt][2] + b0v, x3 = acc[mt][nt][3] + b1v;
            if (sg.act == 1) { x0 = gelu_exact(x0); x1 = gelu_exact(x1); x2 = gelu_exact(x2); x3 = gelu_exact(x3); }
            else if (sg.act == 2) { x0 = sigmoidf(x0); x1 = sigmoidf(x1); x2 = sigmoidf(x2); x3 = sigmoidf(x3); }
            if (sg.cb) {
                unsigned* Cb = (unsigned*)sg.C;
                Cb[(size_t)gm * KP + (gn >> 1)]       = packbf(x0, x1);
                Cb[(size_t)(gm + 8) * KP + (gn >> 1)] = packbf(x2, x3);
            } else {
                float* C = (float*)sg.C;
                *(float2*)&C[(size_t)gm * DD + gn]       = make_float2(x0, x1);
                *(float2*)&C[(size_t)(gm + 8) * DD + gn] = make_float2(x2, x3);
            }
        }
    }
}

// ================= tf32 batched QK^T per (b,h) — round-10 exact =================
#define QK_SMEM (2 * 128 * 68 * 4)
template<int MODE>
__global__ __launch_bounds__(256, 2) void qk_t(
    const float* __restrict__ qb, const float* __restrict__ kb, long kbStride,
    const float* __restrict__ bd, const float* __restrict__ tu, const float* __restrict__ tv,
    float* __restrict__ outp)
{
    extern __shared__ unsigned sh[];
    unsigned (*As)[68] = (unsigned(*)[68])sh;
    unsigned (*Bs)[68] = (unsigned(*)[68])(sh + 128 * 68);
    const int bh = blockIdx.z, b = bh >> 4, h = bh & 15;
    const float* Aq = qb + (size_t)b * SS * DD + h * DH;
    const float* Bk = kb + (size_t)b * kbStride + h * DH;
    const int bs0 = blockIdx.y * 128, bf0 = blockIdx.x * 128;
    const int t = threadIdx.x, lane = t & 31, wid = t >> 5;
    const int wm = wid >> 2, wn = wid & 3;
    const int g = lane >> 2, tg = lane & 3;
    const int lr = t >> 2, q4 = t & 3;

    if (MODE == 0) {
        if (bf0 + 127 < (SS - 128) - bs0) return;
    } else {
        if (bf0 > bs0 + 127 + MM) {
            #pragma unroll
            for (int mt = 0; mt < 4; mt++) {
                int s0g = bs0 + wm * 64 + mt * 16 + g;
                #pragma unroll
                for (int nt = 0; nt < 4; nt++) {
                    int f0g = bf0 + wn * 32 + nt * 8 + tg * 2;
                    #pragma unroll
                    for (int half = 0; half < 2; half++) {
                        size_t rowoff = ((size_t)bh * SS + s0g + half * 8) * FF;
                        *(float2*)&outp[rowoff + f0g] = make_float2(-1e30f, -1e30f);
                    }
                }
            }
            return;
        }
    }

    #pragma unroll
    for (int j = 0; j < 4; j++) {
        int c = (q4 + 4 * j) * 4;
        cpa16(&As[lr][c],      Aq + (size_t)(bs0 + lr) * DD + c);
        cpa16(&As[lr + 64][c], Aq + (size_t)(bs0 + lr + 64) * DD + c);
        cpa16(&Bs[lr][c],      Bk + (size_t)(bf0 + lr) * DD + c);
        cpa16(&Bs[lr + 64][c], Bk + (size_t)(bf0 + lr + 64) * DD + c);
    }
    cpa_commit();

    float acc[4][4][4];
    #pragma unroll
    for (int i = 0; i < 4; i++)
        #pragma unroll
        for (int j = 0; j < 4; j++)
            #pragma unroll
            for (int r = 0; r < 4; r++) acc[i][j][r] = 0.f;

    cpa_wait<0>();
    __syncthreads();

    #pragma unroll
    for (int kk = 0; kk < 64; kk += 8) {
        unsigned af[4][4], bf[4][2];
        #pragma unroll
        for (int mt = 0; mt < 4; mt++) {
            int r = wm * 64 + mt * 16 + g;
            af[mt][0] = As[r][kk + tg];
            af[mt][1] = As[r + 8][kk + tg];
            af[mt][2] = As[r][kk + tg + 4];
            af[mt][3] = As[r + 8][kk + tg + 4];
        }
        #pragma unroll
        for (int nt = 0; nt < 4; nt++) {
            int c = wn * 32 + nt * 8 + g;
            bf[nt][0] = rna(Bs[c][kk + tg]);
            bf[nt][1] = rna(Bs[c][kk + tg + 4]);
        }
        #pragma unroll
        for (int mt = 0; mt < 4; mt++)
            #pragma unroll
            for (int nt = 0; nt < 4; nt++)
                mma8(acc[mt][nt], af[mt], bf[nt]);
    }

    #pragma unroll
    for (int mt = 0; mt < 4; mt++) {
        int s0g = bs0 + wm * 64 + mt * 16 + g;
        #pragma unroll
        for (int nt = 0; nt < 4; nt++) {
            int f0g = bf0 + wn * 32 + nt * 8 + tg * 2;
            #pragma unroll
            for (int half = 0; half < 2; half++) {
                int s_g = s0g + half * 8;
                float y0 = acc[mt][nt][half * 2 + 0];
                float y1 = acc[mt][nt][half * 2 + 1];
                size_t rowoff = ((size_t)bh * SS + s_g) * FF;
                if (MODE == 0) {
                    *(float2*)&outp[rowoff + f0g] = make_float2(y0, y1);
                } else {
                    const float* bdrow = bd + rowoff;
                    const float* tvrow = tv + (size_t)h * FF;
                    const float* turow = tu + (size_t)bh * FF;
                    float v0, v1;
                    int fp0 = f0g + (SS - 1) - s_g;
                    if (f0g > s_g + MM) v0 = -1e30f;
                    else v0 = (y0 + turow[f0g] + bdrow[fp0] + tvrow[fp0]) * 0.03125f;
                    if (f0g + 1 > s_g + MM) v1 = -1e30f;
                    else v1 = (y1 + turow[f0g + 1] + bdrow[fp0 + 1] + tvrow[fp0 + 1]) * 0.03125f;
                    *(float2*)&outp[rowoff + f0g] = make_float2(v0, v1);
                }
            }
        }
    }
}

// ---------------- softmax per row + loss max — round-10 exact ----------------
__global__ __launch_bounds__(256) void softmax_k(
    const float* __restrict__ sc, float* __restrict__ attn,
    unsigned* __restrict__ abf, float* __restrict__ bhmax)
{
    size_t row = blockIdx.x;
    int bh = (int)(row / SS);
    const float4* src = (const float4*)(sc + row * FF);
    float4* dst = (float4*)(attn + row * FF);
    uint2* dstb = (uint2*)(abf + row * (FF / 2));
    int t = threadIdx.x;
    float4 v0 = src[t], v1 = src[t + 256];
    float m = fmaxf(fmaxf(fmaxf(v0.x, v0.y), fmaxf(v0.z, v0.w)),
                    fmaxf(fmaxf(v1.x, v1.y), fmaxf(v1.z, v1.w)));
    #pragma unroll
    for (int o = 16; o; o >>= 1) m = fmaxf(m, __shfl_xor_sync(0xffffffffu, m, o));
    __shared__ float red[8];
    int w = t >> 5, l = t & 31;
    if (l == 0) red[w] = m;
    __syncthreads();
    float mAll = red[0];
    #pragma unroll
    for (int i = 1; i < 8; i++) mAll = fmaxf(mAll, red[i]);
    __syncthreads();

    float e0x = fexp(v0.x - mAll), e0y = fexp(v0.y - mAll);
    float e0z = fexp(v0.z - mAll), e0w = fexp(v0.w - mAll);
    float e1x = fexp(v1.x - mAll), e1y = fexp(v1.y - mAll);
    float e1z = fexp(v1.z - mAll), e1w = fexp(v1.w - mAll);
    float s = e0x + e0y + e0z + e0w + e1x + e1y + e1z + e1w;
    #pragma unroll
    for (int o = 16; o; o >>= 1) s += __shfl_xor_sync(0xffffffffu, s, o);
    if (l == 0) red[w] = s;
    __syncthreads();
    float sAll = 0.f;
    #pragma unroll
    for (int i = 0; i < 8; i++) sAll += red[i];
    float inv = 1.0f / sAll;
    float a0 = e0x * inv, a1 = e0y * inv, a2 = e0z * inv, a3 = e0w * inv;
    float b0 = e1x * inv, b1 = e1y * inv, b2 = e1z * inv, b3 = e1w * inv;
    dst[t]       = make_float4(a0, a1, a2, a3);
    dst[t + 256] = make_float4(b0, b1, b2, b3);
    dstb[t]       = make_uint2(packbf(a0, a1), packbf(a2, a3));
    dstb[t + 256] = make_uint2(packbf(b0, b1), packbf(b2, b3));
    if (t == 0) atomicMax((int*)(bhmax + bh), __float_as_int(inv));
}

// ---------------- v transpose to packed bf16: vt[bh][d][f/2] ----------------
__global__ __launch_bounds__(256) void vtrans_k(
    const float* __restrict__ v, unsigned* __restrict__ vt)
{
    int bh = blockIdx.y, b = bh >> 4, h = bh & 15;
    int f0 = blockIdx.x * 128;
    __shared__ float vs[128][65];
    const float* src = v + (size_t)b * FF * DD + (size_t)f0 * DD + h * DH;
    int t = threadIdx.x;
    #pragma unroll
    for (int j = 0; j < 8; j++) {
        int idx = t + j * 256;
        int row = idx >> 4, c4 = (idx & 15) * 4;
        float4 x = *(const float4*)(src + (size_t)row * DD + c4);
        vs[row][c4] = x.x; vs[row][c4 + 1] = x.y; vs[row][c4 + 2] = x.z; vs[row][c4 + 3] = x.w;
    }
    __syncthreads();
    unsigned* dstb = vt + (size_t)bh * DH * (FF / 2) + f0 / 2;
    #pragma unroll
    for (int j = 0; j < 16; j++) {
        int idx = t + j * 256;
        int d = idx >> 6, fp = idx & 63;
        dstb[(size_t)d * (FF / 2) + fp] = packbf(vs[2 * fp][d], vs[2 * fp + 1][d]);
    }
}

// ================= bf16 attn @ v per (b,h): writes packed bf16 ao (3-stage) =================
__global__ __launch_bounds__(256, 2) void av_b(
    const unsigned* __restrict__ abf, const unsigned* __restrict__ vt, unsigned* __restrict__ aob)
{
    const int bh = blockIdx.y, b = bh >> 4, h = bh & 15;
    const int bs0 = blockIdx.x * 128;
    __shared__ unsigned As[GST][128][20];
    __shared__ unsigned Vs[GST][64][20];
    const int t = threadIdx.x, lane = t & 31, wid = t >> 5;
    const int wm = wid >> 1, wn = wid & 1;
    const int g = lane >> 2, tg = lane & 3;

    const int ar = t >> 1, ac = (t & 1) * 8;
    const int vr = t >> 2, vc = (t & 3) * 4;

    const unsigned* Ap = abf + ((size_t)bh * SS + bs0 + ar) * (FF / 2);
    const unsigned* Vp = vt + ((size_t)bh * DH + vr) * (FF / 2);

    const int nit = min(FF / 32, (bs0 + 1183) >> 5);

    float acc[2][4][4];
    #pragma unroll
    for (int i = 0; i < 2; i++)
        #pragma unroll
        for (int j = 0; j < 4; j++)
            #pragma unroll
            for (int r = 0; r < 4; r++) acc[i][j][r] = 0.f;

    #pragma unroll 1
    for (int s = 0; s < GST - 1; s++) {
        long o = (long)s * 16;
        cpa16(&As[s][ar][ac],     Ap + o + ac);
        cpa16(&As[s][ar][ac + 4], Ap + o + ac + 4);
        cpa16(&Vs[s][vr][vc],     Vp + o + vc);
        cpa_commit();
    }

    for (int it = 0; it < nit; ++it) {
        cpa_wait<GST - 2>();
        __syncthreads();
        if (it + GST - 1 < nit) {
            int st = (it + GST - 1) % GST;
            long o = (long)(it + GST - 1) * 16;
            cpa16(&As[st][ar][ac],     Ap + o + ac);
            cpa16(&As[st][ar][ac + 4], Ap + o + ac + 4);
            cpa16(&Vs[st][vr][vc],     Vp + o + vc);
            cpa_commit();
        }
        const int cur = it % GST;
        #pragma unroll
        for (int kkp = 0; kkp < 16; kkp += 8) {
            unsigned af[2][4], bf[4][2];
            #pragma unroll
            for (int mt = 0; mt < 2; mt++) {
                int r = wm * 32 + mt * 16 + g;
                af[mt][0] = As[cur][r][kkp + tg];
                af[mt][1] = As[cur][r + 8][kkp + tg];
                af[mt][2] = As[cur][r][kkp + tg + 4];
                af[mt][3] = As[cur][r + 8][kkp + tg + 4];
            }
            #pragma unroll
            for (int nt = 0; nt < 4; nt++) {
                int d = wn * 32 + nt * 8 + g;
                bf[nt][0] = Vs[cur][d][kkp + tg];
                bf[nt][1] = Vs[cur][d][kkp + tg + 4];
            }
            #pragma unroll
            for (int mt = 0; mt < 2; mt++)
                #pragma unroll
                for (int nt = 0; nt < 4; nt++)
                    mma16(acc[mt][nt], af[mt], bf[nt]);
        }
    }

    #pragma unroll
    for (int mt = 0; mt < 2; mt++) {
        int gm = bs0 + wm * 32 + mt * 16 + g;
        #pragma unroll
        for (int nt = 0; nt < 4; nt++) {
            int gn = wn * 32 + nt * 8 + tg * 2;
            int col = h * (DH / 2) + (gn >> 1);
            aob[((size_t)b * SS + gm) * KP + col]     = packbf(acc[mt][nt][0], acc[mt][nt][1]);
            aob[((size_t)b * SS + gm + 8) * KP + col] = packbf(acc[mt][nt][2], acc[mt][nt][3]);
        }
    }
}

__global__ void zero32_k(float* p) { if (threadIdx.x < Bb * HH) p[threadIdx.x] = 0.f; }

__global__ void loss_k(const float* __restrict__ bhm, float* __restrict__ out)
{
    int t = threadIdx.x;
    float v = (t < Bb * HH) ? bhm[t] : 0.f;
    #pragma unroll
    for (int o = 16; o; o >>= 1) v += __shfl_xor_sync(0xffffffffu, v, o);
    if (t == 0) out[0] = v * (1.0f / (Bb * HH));
}

// ---------------- launch ----------------
extern "C" void kernel_launch(void* const* d_in, const int* in_sizes, int n_in,
                              void* d_out, int out_size)
{
    const float* inputs = (const float*)d_in[0];
    const float* mem    = (const float*)d_in[1];
    const float* c2     = (const float*)d_in[2];
    const float* c3     = (const float*)d_in[3];
    const float* ln1g   = (const float*)d_in[4];
    const float* ln1b   = (const float*)d_in[5];
    const float* wq     = (const float*)d_in[6];
    const float* wke    = (const float*)d_in[7];
    const float* wkr    = (const float*)d_in[8];
    const float* wv     = (const float*)d_in[9];
    const float* wf     = (const float*)d_in[10];
    const float* up     = (const float*)d_in[11];
    const float* vp     = (const float*)d_in[12];
    const float* ln2g   = (const float*)d_in[13];
    const float* ln2b   = (const float*)d_in[14];
    const float* w1     = (const float*)d_in[15];
    const float* b1     = (const float*)d_in[16];
    const float* w2     = (const float*)d_in[17];
    const float* b2     = (const float*)d_in[18];
    const float* wg1    = (const float*)d_in[19];
    const float* bg1    = (const float*)d_in[20];
    const float* wg2    = (const float*)d_in[21];
    const float* bg2    = (const float*)d_in[22];
    float* out = (float*)d_out;

    float *xt, *q, *k, *v, *rel, *Qr, *bd, *sc, *sg, *g1, *tu, *tv, *wr, *bhm;
    unsigned *wtb, *abf, *vt, *aob, *ibf, *g1b, *h0b, *h1b;
    cudaGetSymbolAddress((void**)&xt,  g_xt);
    cudaGetSymbolAddress((void**)&q,   g_q);
    cudaGetSymbolAddress((void**)&k,   g_k);
    cudaGetSymbolAddress((void**)&v,   g_v);
    cudaGetSymbolAddress((void**)&rel, g_rel);
    cudaGetSymbolAddress((void**)&Qr,  g_Qr);
    cudaGetSymbolAddress((void**)&bd,  g_bd);
    cudaGetSymbolAddress((void**)&sc,  g_sc);
    cudaGetSymbolAddress((void**)&sg,  g_sg);
    cudaGetSymbolAddress((void**)&g1,  g_g1);
    cudaGetSymbolAddress((void**)&tu,  g_tu);
    cudaGetSymbolAddress((void**)&tv,  g_tv);
    cudaGetSymbolAddress((void**)&wr,  g_wr);
    cudaGetSymbolAddress((void**)&wtb, g_wtb);
    cudaGetSymbolAddress((void**)&abf, g_abf);
    cudaGetSymbolAddress((void**)&vt,  g_vt);
    cudaGetSymbolAddress((void**)&aob, g_aob);
    cudaGetSymbolAddress((void**)&ibf, g_ibf);
    cudaGetSymbolAddress((void**)&g1b, g_g1b);
    cudaGetSymbolAddress((void**)&h0b, g_h0b);
    cudaGetSymbolAddress((void**)&h1b, g_h1b);
    cudaGetSymbolAddress((void**)&bhm, g_bhmax);

    static bool init = false;
    static cudaStream_t st1, st2, st3;
    static cudaEvent_t eRoot, eW4, eRel, eT4, eVT, ePD, eG1;
    if (!init) {
        cudaFuncSetAttribute(gemm_t4,     cudaFuncAttributeMaxDynamicSharedMemorySize, GEMM_SMEM);
        cudaFuncSetAttribute(gemm_b2,     cudaFuncAttributeMaxDynamicSharedMemorySize, GB_SMEM);
        cudaFuncSetAttribute(gemm_bf<0>,  cudaFuncAttributeMaxDynamicSharedMemorySize, GB_SMEM);
        cudaFuncSetAttribute(gemm_bf<1>,  cudaFuncAttributeMaxDynamicSharedMemorySize, GB_SMEM);
        cudaFuncSetAttribute(gemm_bf<2>,  cudaFuncAttributeMaxDynamicSharedMemorySize, GB_SMEM);
        cudaFuncSetAttribute(qk_t<0>,     cudaFuncAttributeMaxDynamicSharedMemorySize, QK_SMEM);
        cudaFuncSetAttribute(qk_t<1>,     cudaFuncAttributeMaxDynamicSharedMemorySize, QK_SMEM);
        cudaStreamCreateWithFlags(&st1, cudaStreamNonBlocking);
        cudaStreamCreateWithFlags(&st2, cudaStreamNonBlocking);
        cudaStreamCreateWithFlags(&st3, cudaStreamNonBlocking);
        cudaEventCreateWithFlags(&eRoot, cudaEventDisableTiming);
        cudaEventCreateWithFlags(&eW4,   cudaEventDisableTiming);
        cudaEventCreateWithFlags(&eRel,  cudaEventDisableTiming);
        cudaEventCreateWithFlags(&eT4,   cudaEventDisableTiming);
        cudaEventCreateWithFlags(&eVT,   cudaEventDisableTiming);
        cudaEventCreateWithFlags(&ePD,   cudaEventDisableTiming);
        cudaEventCreateWithFlags(&eG1,   cudaEventDisableTiming);
        init = true;
    }

    const long OUT_N  = (long)Bb * SS * DD;
    const long ATTN_N = (long)Bb * HH * SS * FF;
    bool has_attn = ((long)out_size >= OUT_N + ATTN_N);
    bool has_loss = ((long)out_size >= OUT_N + ATTN_N + 1);
    float* attn = has_attn ? (out + OUT_N) : bd;

    const long WN = (long)DD * DD;
    float* rwq  = wr + 0 * WN; float* rwke = wr + 1 * WN;
    float* rwkr = wr + 2 * WN; float* rwv  = wr + 3 * WN;
    unsigned* twf  = wtb + 0 * DD * KP; unsigned* tw1  = wtb + 1 * DD * KP;
    unsigned* tw2  = wtb + 2 * DD * KP; unsigned* twg1 = wtb + 3 * DD * KP;
    unsigned* twg2 = wtb + 4 * DD * KP;

    // ---- fork root ----
    zero32_k<<<1, 32>>>(bhm);
    cudaEventRecord(eRoot, 0);

    // ---- st1 (forked): attention-weight prep ----
    cudaStreamWaitEvent(st1, eRoot, 0);
    {
        Ptr4 p4; p4.p[0] = wq; p4.p[1] = wke; p4.p[2] = wkr; p4.p[3] = wv;
        dim3 g((int)(WN / 4 / 256), 4);
        wround4_k<<<g, 256, 0, st1>>>(p4, wr);
        cudaEventRecord(eW4, st1);
    }

    // ---- st2 (forked): FFN weight prep + ibf + gate1 GEMM ----
    cudaStreamWaitEvent(st2, eRoot, 0);
    {
        Ptr5 p5; p5.p[0] = wf; p5.p[1] = w1; p5.p[2] = w2; p5.p[3] = wg1; p5.p[4] = wg2;
        dim3 g(128, 5);
        wtrans5_k<<<g, 256, 0, st2>>>(p5, wtb);
        int n = Bb * SS * KP;
        tobf_k<<<(n + 255) / 256, 256, 0, st2>>>((const float2*)inputs, ibf, n);
        dim3 gb(DD / 128, (Bb * SS) / 128);
        gemm_bf<0><<<gb, 256, GB_SMEM, st2>>>(ibf, twg1, bg1, nullptr, nullptr, sg, nullptr);
        cudaEventRecord(eG1, st2);
    }

    // ---- st3 (forked): rel pick ----
    cudaStreamWaitEvent(st3, eRoot, 0);
    {
        const int n4 = (FF * DD) / 4;
        pick_rel_k<<<(n4 + 255) / 256, 256, 0, st3>>>(c2, c3, rel);
        cudaEventRecord(eRel, st3);
    }

    // ---- s0: LN1 (overlaps the forks) ----
    ln_concat_k<<<Bb * FF, 256>>>(inputs, mem, ln1g, ln1b, xt);

    // ---- s0: fused q/k/v/Qr ----
    cudaStreamWaitEvent(0, eW4, 0);
    cudaStreamWaitEvent(0, eRel, 0);
    {
        T4 p;
        p.xt = xt; p.rel = rel;
        p.wq = rwq; p.wke = rwke; p.wv = rwv; p.wkr = rwkr;
        p.q = q; p.k = k; p.v = v; p.Qr = Qr;
        dim3 g(DD / 128, 96);
        gemm_t4<<<g, 256, GEMM_SMEM>>>(p);
        cudaEventRecord(eT4, 0);
    }

    // ---- st1 (refork): vtrans ----
    cudaStreamWaitEvent(st1, eT4, 0);
    {
        dim3 g(FF / 128, Bb * HH);
        vtrans_k<<<g, 256, 0, st1>>>(v, vt);
        cudaEventRecord(eVT, st1);
    }
    // ---- st3 (refork): pdot tu/tv ----
    cudaStreamWaitEvent(st3, eT4, 0);
    {
        dim3 gtu(FF / 8, Bb * HH), gtv(FF / 8, HH);
        pdot_k<<<gtu, 256, 0, st3>>>(up, k, (long)FF * DD, 1, tu);
        pdot_k<<<gtv, 256, 0, st3>>>(vp, Qr, 0, 0, tv);
        cudaEventRecord(ePD, st3);
    }

    // ---- s0: qk0 / qk1 / softmax / av ----
    {
        dim3 g(FF / 128, SS / 128, Bb * HH);
        qk_t<0><<<g, 256, QK_SMEM>>>(q, Qr, 0L, nullptr, nullptr, nullptr, bd);
    }
    cudaStreamWaitEvent(0, ePD, 0);
    {
        dim3 g(FF / 128, SS / 128, Bb * HH);
        qk_t<1><<<g, 256, QK_SMEM>>>(q, k, (long)FF * DD, bd, tu, tv, sc);
    }

    softmax_k<<<Bb * HH * SS, 256>>>(sc, attn, abf, bhm);

    cudaStreamWaitEvent(0, eVT, 0);
    {
        dim3 g(SS / 128, Bb * HH);
        av_b<<<g, 256>>>(abf, vt, aob);
    }

    // ---- s0: FFN tail with fused epilogues ----
    cudaStreamWaitEvent(0, eG1, 0);
    dim3 gb(DD / 128, (Bb * SS) / 128);
    // g1 = inputs + sg * gelu(ao@wf); writes g1 fp32 + g1b bf16
    gemm_bf<1><<<gb, 256, GB_SMEM>>>(aob, twf, nullptr, inputs, sg, g1, g1b);
    ln_bf_k<<<Bb * SS, 256>>>(g1, ln2g, ln2b, h0b);
    {
        B2 p;
        p.s0.A = h0b; p.s0.Wt = tw1;  p.s0.bias = b1;  p.s0.C = h1b; p.s0.act = 1; p.s0.cb = 1;
        p.s1.A = g1b; p.s1.Wt = twg2; p.s1.bias = bg2; p.s1.C = sg;  p.s1.act = 2; p.s1.cb = 0;
        dim3 g(DD / 128, 32);
        gemm_b2<<<g, 256, GB_SMEM>>>(p);
    }
    // out = g1 + sg * gelu(h1@w2 + b2)
    gemm_bf<2><<<gb, 256, GB_SMEM>>>(h1b, tw2, b2, g1, sg, out, nullptr);

    if (has_loss) loss_k<<<1, 32>>>(bhm, out + OUT_N + ATTN_N);
}

// round 17
// speedup vs baseline: 1.0118x; 1.0118x over previous
#include <cuda_runtime.h>
#include <cuda_bf16.h>
#include <math.h>

#define Bb 2
#define SS 1024
#define MM 1024
#define DD 1024
#define HH 16
#define DH 64
#define FF 2048
#define KP (DD/2)

// ---------------- scratch (device globals; no allocation allowed) ----------------
__device__ float g_xt[(size_t)Bb*FF*DD];
__device__ float g_q [(size_t)Bb*SS*DD];
__device__ float g_k [(size_t)Bb*FF*DD];
__device__ float g_v [(size_t)Bb*FF*DD];
__device__ float g_rel[(size_t)FF*DD];
__device__ float g_Qr[(size_t)FF*DD];
__device__ float g_bd[(size_t)Bb*HH*SS*FF];
__device__ float g_sc[(size_t)Bb*HH*SS*FF];
__device__ float g_sg[(size_t)Bb*SS*DD];
__device__ float g_g1[(size_t)Bb*SS*DD];
__device__ float g_tu[(size_t)Bb*HH*FF];
__device__ float g_tv[(size_t)HH*FF];
__device__ float g_wr[(size_t)4*DD*DD];
__device__ unsigned g_wtb[(size_t)5*DD*KP];
__device__ unsigned g_abf[(size_t)Bb*HH*SS*(FF/2)];
__device__ unsigned g_vt[(size_t)Bb*HH*DH*(FF/2)];
__device__ unsigned g_aob[(size_t)Bb*SS*KP];
__device__ unsigned g_ibf[(size_t)Bb*SS*KP];
__device__ unsigned g_g1b[(size_t)Bb*SS*KP];
__device__ unsigned g_h0b[(size_t)Bb*SS*KP];
__device__ unsigned g_h1b[(size_t)Bb*SS*KP];
__device__ float g_bhmax[Bb*HH];

// ---------------- helpers ----------------
__device__ __forceinline__ float gelu_exact(float x) {
    return 0.5f * x * (1.0f + erff(x * 0.70710678118654752440f));
}
__device__ __forceinline__ float fexp(float x) {
    float y = x * 1.4426950408889634f;
    y = fminf(fmaxf(y, -126.0f), 126.0f);
    float n = rintf(y);
    float f = y - n;
    float p = 1.54035304e-4f;
    p = fmaf(p, f, 1.33335581e-3f);
    p = fmaf(p, f, 9.61812911e-3f);
    p = fmaf(p, f, 5.55041087e-2f);
    p = fmaf(p, f, 2.40226512e-1f);
    p = fmaf(p, f, 6.93147182e-1f);
    p = fmaf(p, f, 1.0f);
    return __int_as_float(((int)n + 127) << 23) * p;
}
__device__ __forceinline__ float sigmoidf(float x) {
    return 1.0f / (1.0f + fexp(-x));
}
__device__ __forceinline__ unsigned rna(unsigned x) {
    unsigned u;
    asm("cvt.rna.tf32.f32 %0, %1;" : "=r"(u) : "f"(__uint_as_float(x)));
    return u;
}
__device__ __forceinline__ float rnaf(float x) {
    unsigned u;
    asm("cvt.rna.tf32.f32 %0, %1;" : "=r"(u) : "f"(x));
    return __uint_as_float(u);
}
__device__ __forceinline__ void mma8(float* c, const unsigned* a, const unsigned* b) {
    asm volatile("mma.sync.aligned.m16n8k8.row.col.f32.tf32.tf32.f32 "
        "{%0,%1,%2,%3}, {%4,%5,%6,%7}, {%8,%9}, {%0,%1,%2,%3};"
        : "+f"(c[0]), "+f"(c[1]), "+f"(c[2]), "+f"(c[3])
        : "r"(a[0]), "r"(a[1]), "r"(a[2]), "r"(a[3]), "r"(b[0]), "r"(b[1]));
}
__device__ __forceinline__ void mma16(float* c, const unsigned* a, const unsigned* b) {
    asm volatile("mma.sync.aligned.m16n8k16.row.col.f32.bf16.bf16.f32 "
        "{%0,%1,%2,%3}, {%4,%5,%6,%7}, {%8,%9}, {%0,%1,%2,%3};"
        : "+f"(c[0]), "+f"(c[1]), "+f"(c[2]), "+f"(c[3])
        : "r"(a[0]), "r"(a[1]), "r"(a[2]), "r"(a[3]), "r"(b[0]), "r"(b[1]));
}
__device__ __forceinline__ void cpa16(void* smem, const void* gmem) {
    unsigned s = (unsigned)__cvta_generic_to_shared(smem);
    asm volatile("cp.async.ca.shared.global [%0], [%1], 16;" :: "r"(s), "l"(gmem));
}
__device__ __forceinline__ void cpa_commit() { asm volatile("cp.async.commit_group;"); }
template<int N_> __device__ __forceinline__ void cpa_wait() {
    asm volatile("cp.async.wait_group %0;" :: "n"(N_));
}
__device__ __forceinline__ unsigned packbf(float a, float b) {
    __nv_bfloat162 h = __floats2bfloat162_rn(a, b);
    return *(unsigned*)&h;
}

// ---------------- pre-round 4 attention weights (tf32 values) ----------------
struct Ptr4 { const float* p[4]; };
__global__ __launch_bounds__(256) void wround4_k(Ptr4 srcs, float* __restrict__ d)
{
    int m = blockIdx.y;
    int i = blockIdx.x * 256 + threadIdx.x;
    const float4* s = (const float4*)srcs.p[m];
    float4 v = s[i];
    v.x = rnaf(v.x); v.y = rnaf(v.y); v.z = rnaf(v.z); v.w = rnaf(v.w);
    ((float4*)(d + (size_t)m * DD * DD))[i] = v;
}

// ---------------- transpose+pack 5 FFN weights to bf16 Wt[n][k/2] ----------------
struct Ptr5 { const float* p[5]; };
__global__ __launch_bounds__(256) void wtrans5_k(Ptr5 srcs, unsigned* __restrict__ d)
{
    int m = blockIdx.y;
    int tile = blockIdx.x;
    int kt = tile >> 3, nt = tile & 7;
    int k0 = kt * 64, n0 = nt * 128;
    __shared__ float vs[64][129];
    const float* W = srcs.p[m];
    int t = threadIdx.x;
    #pragma unroll
    for (int j = 0; j < 8; j++) {
        int idx = t + j * 256;
        int kr = idx >> 5, nc4 = (idx & 31) * 4;
        float4 x = *(const float4*)(W + (size_t)(k0 + kr) * DD + n0 + nc4);
        vs[kr][nc4] = x.x; vs[kr][nc4 + 1] = x.y; vs[kr][nc4 + 2] = x.z; vs[kr][nc4 + 3] = x.w;
    }
    __syncthreads();
    unsigned* dst = d + (size_t)m * DD * KP;
    #pragma unroll
    for (int j = 0; j < 16; j++) {
        int idx = t + j * 256;
        int n = idx >> 5, kp = idx & 31;
        dst[(size_t)(n0 + n) * KP + k0 / 2 + kp] = packbf(vs[2 * kp][n], vs[2 * kp + 1][n]);
    }
}

// ---------------- fp32 -> packed bf16 ----------------
__global__ __launch_bounds__(256) void tobf_k(
    const float2* __restrict__ s, unsigned* __restrict__ d, int n)
{
    int i = blockIdx.x * 256 + threadIdx.x;
    if (i < n) { float2 v = s[i]; d[i] = packbf(v.x, v.y); }
}

// ---------------- pick rel_enc among two same-sized candidates ----------------
__global__ __launch_bounds__(256) void pick_rel_k(
    const float* __restrict__ c2, const float* __restrict__ c3, float* __restrict__ dst)
{
    __shared__ int isrel2;
    if (threadIdx.x == 0) {
        int r = 0;
        #pragma unroll
        for (int i = 0; i < 64; i++) {
            float v = c2[i];
            if (v != 0.0f && v != 1.0f) { r = 1; break; }
        }
        isrel2 = r;
    }
    __syncthreads();
    const float4* src = (const float4*)(isrel2 ? c2 : c3);
    int i = blockIdx.x * 256 + threadIdx.x;
    const int n4 = (FF * DD) / 4;
    if (i < n4) {
        float4 v = src[i];
        v.x = rnaf(v.x); v.y = rnaf(v.y); v.z = rnaf(v.z); v.w = rnaf(v.w);
        ((float4*)dst)[i] = v;
    }
}

// ---------------- layernorms ----------------
__global__ __launch_bounds__(256) void ln_concat_k(
    const float* __restrict__ inp, const float* __restrict__ mem,
    const float* __restrict__ g, const float* __restrict__ b,
    float* __restrict__ out)
{
    int row = blockIdx.x;
    int bb = row / FF; int fr = row - bb * FF;
    const float* src = (fr < MM) ? (mem + ((size_t)bb*MM + fr) * DD)
                                 : (inp + ((size_t)bb*SS + (fr - MM)) * DD);
    float* dst = out + (size_t)row * DD;
    int t = threadIdx.x;
    float4 x = ((const float4*)src)[t];
    float s  = x.x + x.y + x.z + x.w;
    float q  = x.x*x.x + x.y*x.y + x.z*x.z + x.w*x.w;
    #pragma unroll
    for (int o = 16; o; o >>= 1) {
        s += __shfl_xor_sync(0xffffffffu, s, o);
        q += __shfl_xor_sync(0xffffffffu, q, o);
    }
    __shared__ float rs[8], rq[8];
    int w = t >> 5, l = t & 31;
    if (l == 0) { rs[w] = s; rq[w] = q; }
    __syncthreads();
    float st = 0.f, qt = 0.f;
    #pragma unroll
    for (int i = 0; i < 8; i++) { st += rs[i]; qt += rq[i]; }
    float mean = st * (1.0f / DD);
    float var  = qt * (1.0f / DD) - mean * mean;
    float r = rsqrtf(var + 1e-5f);
    float4 gg = ((const float4*)g)[t];
    float4 bv = ((const float4*)b)[t];
    float4 y;
    y.x = rnaf((x.x - mean) * r * gg.x + bv.x);
    y.y = rnaf((x.y - mean) * r * gg.y + bv.y);
    y.z = rnaf((x.z - mean) * r * gg.z + bv.z);
    y.w = rnaf((x.w - mean) * r * gg.w + bv.w);
    ((float4*)dst)[t] = y;
}

__global__ __launch_bounds__(256) void ln_bf_k(
    const float* __restrict__ a,
    const float* __restrict__ g, const float* __restrict__ b,
    unsigned* __restrict__ outb)
{
    int row = blockIdx.x;
    const float* src = a + (size_t)row * DD;
    int t = threadIdx.x;
    float4 x = ((const float4*)src)[t];
    float s  = x.x + x.y + x.z + x.w;
    float q  = x.x*x.x + x.y*x.y + x.z*x.z + x.w*x.w;
    #pragma unroll
    for (int o = 16; o; o >>= 1) {
        s += __shfl_xor_sync(0xffffffffu, s, o);
        q += __shfl_xor_sync(0xffffffffu, q, o);
    }
    __shared__ float rs[8], rq[8];
    int w = t >> 5, l = t & 31;
    if (l == 0) { rs[w] = s; rq[w] = q; }
    __syncthreads();
    float st = 0.f, qt = 0.f;
    #pragma unroll
    for (int i = 0; i < 8; i++) { st += rs[i]; qt += rq[i]; }
    float mean = st * (1.0f / DD);
    float var  = qt * (1.0f / DD) - mean * mean;
    float r = rsqrtf(var + 1e-5f);
    float4 gg = ((const float4*)g)[t];
    float4 bv = ((const float4*)b)[t];
    float y0 = (x.x - mean) * r * gg.x + bv.x;
    float y1 = (x.y - mean) * r * gg.y + bv.y;
    float y2 = (x.z - mean) * r * gg.z + bv.z;
    float y3 = (x.w - mean) * r * gg.w + bv.w;
    ((uint2*)(outb + (size_t)row * KP))[t] = make_uint2(packbf(y0, y1), packbf(y2, y3));
}

// ---------------- rank-1 terms ----------------
__global__ __launch_bounds__(256) void pdot_k(
    const float* __restrict__ par, const float* __restrict__ mat,
    long zStride, int useB, float* __restrict__ outp)
{
    int z = blockIdx.y;
    int h = useB ? (z & 15) : z;
    long base = useB ? (long)(z >> 4) * zStride : 0;
    int f = blockIdx.x * 8 + (threadIdx.x >> 5);
    int lane = threadIdx.x & 31;
    float2 pv = *(const float2*)(par + h * DH + lane * 2);
    float2 mv = *(const float2*)(mat + base + (size_t)f * DD + h * DH + lane * 2);
    float s = pv.x * mv.x + pv.y * mv.y;
    #pragma unroll
    for (int o = 16; o; o >>= 1) s += __shfl_xor_sync(0xffffffffu, s, o);
    if (lane == 0) outp[(size_t)z * FF + f] = s;
}

// ================= fused tf32 GEMM: q,k,v,Qr (256 thr, 3-stage cp.async) =================
#define GST 3
#define GT  3
#define GEMM_SMEM (GT * (128*20 + 16*136) * 4)
struct T4 {
    const float* xt; const float* rel;
    const float* wq; const float* wke; const float* wv; const float* wkr;
    float* q; float* k; float* v; float* Qr;
};
__global__ __launch_bounds__(256, 2) void gemm_t4(T4 p)
{
    extern __shared__ unsigned sh[];
    unsigned (*As)[128][20] = (unsigned(*)[128][20])sh;
    unsigned (*Ws)[16][136] = (unsigned(*)[16][136])(sh + GT * 128 * 20);
    const int y = blockIdx.y;
    const float* A; const float* W; float* C; int cr;
    if (y < 16) {
        int b = y >> 3, rt = y & 7;
        A = p.xt + (size_t)b * FF * DD + (size_t)MM * DD + (size_t)rt * 128 * DD;
        C = p.q  + (size_t)b * SS * DD + (size_t)rt * 128 * DD;
        W = p.wq; cr = 1;
    } else if (y < 48) {
        int rt = y - 16;
        A = p.xt + (size_t)rt * 128 * DD;
        C = p.k  + (size_t)rt * 128 * DD;
        W = p.wke; cr = 0;
    } else if (y < 80) {
        int rt = y - 48;
        A = p.xt + (size_t)rt * 128 * DD;
        C = p.v  + (size_t)rt * 128 * DD;
        W = p.wv; cr = 1;
    } else {
        int rt = y - 80;
        A = p.rel + (size_t)rt * 128 * DD;
        C = p.Qr  + (size_t)rt * 128 * DD;
        W = p.wkr; cr = 0;
    }
    const int bn = blockIdx.x * 128;
    const int t = threadIdx.x, lane = t & 31, wid = t >> 5;
    const int wm = wid >> 2, wn = wid & 3;
    const int g = lane >> 2, tg = lane & 3;
    const int am = t >> 2, ak = (t & 3) * 4;
    const float* Ap0 = A + (size_t)am * DD + ak;
    const float* Ap1 = Ap0 + (size_t)64 * DD;
    const int wk = t >> 5, wnc = (t & 31) * 4;
    const float* Wp0 = W + (size_t)wk * DD + bn + wnc;
    const float* Wp1 = Wp0 + (size_t)8 * DD;

    float acc[4][4][4];
    #pragma unroll
    for (int i = 0; i < 4; i++)
        #pragma unroll
        for (int j = 0; j < 4; j++)
            #pragma unroll
            for (int r = 0; r < 4; r++) acc[i][j][r] = 0.f;

    const int NIT = DD >> 4;
    #pragma unroll 1
    for (int s = 0; s < GT - 1; s++) {
        long o = (long)s * 16;
        cpa16(&As[s][am][ak],      Ap0 + o);
        cpa16(&As[s][am + 64][ak], Ap1 + o);
        cpa16(&Ws[s][wk][wnc],     Wp0 + o * DD);
        cpa16(&Ws[s][wk + 8][wnc], Wp1 + o * DD);
        cpa_commit();
    }

    for (int it = 0; it < NIT; ++it) {
        cpa_wait<GT - 2>();
        __syncthreads();
        if (it + GT - 1 < NIT) {
            int st = (it + GT - 1) % GT;
            long o = (long)(it + GT - 1) * 16;
            cpa16(&As[st][am][ak],      Ap0 + o);
            cpa16(&As[st][am + 64][ak], Ap1 + o);
            cpa16(&Ws[st][wk][wnc],     Wp0 + o * DD);
            cpa16(&Ws[st][wk + 8][wnc], Wp1 + o * DD);
            cpa_commit();
        }
        const int cur = it % GT;
        #pragma unroll
        for (int kk = 0; kk < 16; kk += 8) {
            unsigned af[4][4], bf[4][2];
            #pragma unroll
            for (int mt = 0; mt < 4; mt++) {
                int r = wm * 64 + mt * 16 + g;
                af[mt][0] = As[cur][r][kk + tg];
                af[mt][1] = As[cur][r + 8][kk + tg];
                af[mt][2] = As[cur][r][kk + tg + 4];
                af[mt][3] = As[cur][r + 8][kk + tg + 4];
            }
            #pragma unroll
            for (int nt = 0; nt < 4; nt++) {
                int c = wn * 32 + nt * 8 + g;
                bf[nt][0] = Ws[cur][kk + tg][c];
                bf[nt][1] = Ws[cur][kk + tg + 4][c];
            }
            #pragma unroll
            for (int mt = 0; mt < 4; mt++)
                #pragma unroll
                for (int nt = 0; nt < 4; nt++)
                    mma8(acc[mt][nt], af[mt], bf[nt]);
        }
    }

    #pragma unroll
    for (int mt = 0; mt < 4; mt++) {
        int gm = wm * 64 + mt * 16 + g;
        #pragma unroll
        for (int nt = 0; nt < 4; nt++) {
            int gn = bn + wn * 32 + nt * 8 + tg * 2;
            float x0 = acc[mt][nt][0], x1 = acc[mt][nt][1];
            float x2 = acc[mt][nt][2], x3 = acc[mt][nt][3];
            if (cr) { x0 = rnaf(x0); x1 = rnaf(x1); x2 = rnaf(x2); x3 = rnaf(x3); }
            *(float2*)&C[(size_t)gm * DD + gn]       = make_float2(x0, x1);
            *(float2*)&C[(size_t)(gm + 8) * DD + gn] = make_float2(x2, x3);
        }
    }
}

// ================= bf16 FFN GEMM with fused epilogues (3-stage) =================
// EPI 0: out1 = sigmoid(acc + bias)                          (gate1 -> sg)
// EPI 1: g = e1 + e2 * gelu(acc); out1 = g fp32, out2 = g bf16  (wf + gate-apply)
// EPI 2: out1 = e1 + e2 * gelu(acc + bias)                   (w2 + final gate)
#define GB_SMEM (GT * 128 * 20 * 2 * 4)
template<int EPI>
__global__ __launch_bounds__(256, 2) void gemm_bf(
    const unsigned* __restrict__ A, const unsigned* __restrict__ Wt,
    const float* __restrict__ bias,
    const float* __restrict__ e1, const float* __restrict__ e2,
    float* __restrict__ out1, unsigned* __restrict__ out2)
{
    extern __shared__ unsigned sh[];
    unsigned (*As)[128][20] = (unsigned(*)[128][20])sh;
    unsigned (*Ws)[128][20] = (unsigned(*)[128][20])(sh + GT * 128 * 20);
    const int bm = blockIdx.y * 128, bn = blockIdx.x * 128;
    const int t = threadIdx.x, lane = t & 31, wid = t >> 5;
    const int wm = wid >> 2, wn = wid & 3;
    const int g = lane >> 2, tg = lane & 3;
    const int ar = t >> 1, ac = (t & 1) * 8;
    const unsigned* Ap = A  + (size_t)(bm + ar) * KP + ac;
    const unsigned* Wp = Wt + (size_t)(bn + ar) * KP + ac;

    float acc[4][4][4];
    #pragma unroll
    for (int i = 0; i < 4; i++)
        #pragma unroll
        for (int j = 0; j < 4; j++)
            #pragma unroll
            for (int r = 0; r < 4; r++) acc[i][j][r] = 0.f;

    const int NIT = KP / 16;
    #pragma unroll 1
    for (int s = 0; s < GT - 1; s++) {
        long o = (long)s * 16;
        cpa16(&As[s][ar][ac],     Ap + o);
        cpa16(&As[s][ar][ac + 4], Ap + o + 4);
        cpa16(&Ws[s][ar][ac],     Wp + o);
        cpa16(&Ws[s][ar][ac + 4], Wp + o + 4);
        cpa_commit();
    }

    for (int it = 0; it < NIT; ++it) {
        cpa_wait<GT - 2>();
        __syncthreads();
        if (it + GT - 1 < NIT) {
            int st = (it + GT - 1) % GT;
            long o = (long)(it + GT - 1) * 16;
            cpa16(&As[st][ar][ac],     Ap + o);
            cpa16(&As[st][ar][ac + 4], Ap + o + 4);
            cpa16(&Ws[st][ar][ac],     Wp + o);
            cpa16(&Ws[st][ar][ac + 4], Wp + o + 4);
            cpa_commit();
        }
        const int cur = it % GT;
        #pragma unroll
        for (int kkp = 0; kkp < 16; kkp += 8) {
            unsigned af[4][4], bf[4][2];
            #pragma unroll
            for (int mt = 0; mt < 4; mt++) {
                int r = wm * 64 + mt * 16 + g;
                af[mt][0] = As[cur][r][kkp + tg];
                af[mt][1] = As[cur][r + 8][kkp + tg];
                af[mt][2] = As[cur][r][kkp + tg + 4];
                af[mt][3] = As[cur][r + 8][kkp + tg + 4];
            }
            #pragma unroll
            for (int nt = 0; nt < 4; nt++) {
                int c = wn * 32 + nt * 8 + g;
                bf[nt][0] = Ws[cur][c][kkp + tg];
                bf[nt][1] = Ws[cur][c][kkp + tg + 4];
            }
            #pragma unroll
            for (int mt = 0; mt < 4; mt++)
                #pragma unroll
                for (int nt = 0; nt < 4; nt++)
                    mma16(acc[mt][nt], af[mt], bf[nt]);
        }
    }

    #pragma unroll
    for (int mt = 0; mt < 4; mt++) {
        int gm = bm + wm * 64 + mt * 16 + g;
        #pragma unroll
        for (int nt = 0; nt < 4; nt++) {
            int gn = bn + wn * 32 + nt * 8 + tg * 2;
            float b0v = bias ? bias[gn]     : 0.f;
            float b1v = bias ? bias[gn + 1] : 0.f;
            #pragma unroll
            for (int half = 0; half < 2; half++) {
                int gmr = gm + half * 8;
                float x0 = acc[mt][nt][half * 2 + 0] + b0v;
                float x1 = acc[mt][nt][half * 2 + 1] + b1v;
                if (EPI == 0) {
                    x0 = sigmoidf(x0); x1 = sigmoidf(x1);
                    *(float2*)&out1[(size_t)gmr * DD + gn] = make_float2(x0, x1);
                } else if (EPI == 1) {
                    x0 = gelu_exact(x0); x1 = gelu_exact(x1);
                    float2 iv = *(const float2*)&e1[(size_t)gmr * DD + gn];
                    float2 sv = *(const float2*)&e2[(size_t)gmr * DD + gn];
                    float g0 = iv.x + sv.x * x0;
                    float g1v = iv.y + sv.y * x1;
                    *(float2*)&out1[(size_t)gmr * DD + gn] = make_float2(g0, g1v);
                    out2[(size_t)gmr * KP + (gn >> 1)] = packbf(g0, g1v);
                } else {
                    x0 = gelu_exact(x0); x1 = gelu_exact(x1);
                    float2 iv = *(const float2*)&e1[(size_t)gmr * DD + gn];
                    float2 sv = *(const float2*)&e2[(size_t)gmr * DD + gn];
                    *(float2*)&out1[(size_t)gmr * DD + gn] =
                        make_float2(iv.x + sv.x * x0, iv.y + sv.y * x1);
                }
            }
        }
    }
}

// ================= bf16 dual-segment GEMM (h1 + gate2), 3-stage =================
struct BSeg { const unsigned* A; const unsigned* Wt; const float* bias; void* C; int act; int cb; };
struct B2 { BSeg s0, s1; };
__global__ __launch_bounds__(256, 2) void gemm_b2(B2 p)
{
    extern __shared__ unsigned sh[];
    unsigned (*As)[128][20] = (unsigned(*)[128][20])sh;
    unsigned (*Ws)[128][20] = (unsigned(*)[128][20])(sh + GT * 128 * 20);
    const int y = blockIdx.y;
    BSeg sg = (y < 16) ? p.s0 : p.s1;
    const int rt = (y < 16) ? y : y - 16;
    const int bm = rt * 128, bn = blockIdx.x * 128;
    const int t = threadIdx.x, lane = t & 31, wid = t >> 5;
    const int wm = wid >> 2, wn = wid & 3;
    const int g = lane >> 2, tg = lane & 3;
    const int ar = t >> 1, ac = (t & 1) * 8;
    const unsigned* Ap = sg.A  + (size_t)(bm + ar) * KP + ac;
    const unsigned* Wp = sg.Wt + (size_t)(bn + ar) * KP + ac;

    float acc[4][4][4];
    #pragma unroll
    for (int i = 0; i < 4; i++)
        #pragma unroll
        for (int j = 0; j < 4; j++)
            #pragma unroll
            for (int r = 0; r < 4; r++) acc[i][j][r] = 0.f;

    const int NIT = KP / 16;
    #pragma unroll 1
    for (int s = 0; s < GT - 1; s++) {
        long o = (long)s * 16;
        cpa16(&As[s][ar][ac],     Ap + o);
        cpa16(&As[s][ar][ac + 4], Ap + o + 4);
        cpa16(&Ws[s][ar][ac],     Wp + o);
        cpa16(&Ws[s][ar][ac + 4], Wp + o + 4);
        cpa_commit();
    }

    for (int it = 0; it < NIT; ++it) {
        cpa_wait<GT - 2>();
        __syncthreads();
        if (it + GT - 1 < NIT) {
            int st = (it + GT - 1) % GT;
            long o = (long)(it + GT - 1) * 16;
            cpa16(&As[st][ar][ac],     Ap + o);
            cpa16(&As[st][ar][ac + 4], Ap + o + 4);
            cpa16(&Ws[st][ar][ac],     Wp + o);
            cpa16(&Ws[st][ar][ac + 4], Wp + o + 4);
            cpa_commit();
        }
        const int cur = it % GT;
        #pragma unroll
        for (int kkp = 0; kkp < 16; kkp += 8) {
            unsigned af[4][4], bf[4][2];
            #pragma unroll
            for (int mt = 0; mt < 4; mt++) {
                int r = wm * 64 + mt * 16 + g;
                af[mt][0] = As[cur][r][kkp + tg];
                af[mt][1] = As[cur][r + 8][kkp + tg];
                af[mt][2] = As[cur][r][kkp + tg + 4];
                af[mt][3] = As[cur][r + 8][kkp + tg + 4];
            }
            #pragma unroll
            for (int nt = 0; nt < 4; nt++) {
                int c = wn * 32 + nt * 8 + g;
                bf[nt][0] = Ws[cur][c][kkp + tg];
                bf[nt][1] = Ws[cur][c][kkp + tg + 4];
            }
            #pragma unroll
            for (int mt = 0; mt < 4; mt++)
                #pragma unroll
                for (int nt = 0; nt < 4; nt++)
                    mma16(acc[mt][nt], af[mt], bf[nt]);
        }
    }

    #pragma unroll
    for (int mt = 0; mt < 4; mt++) {
        int gm = bm + wm * 64 + mt * 16 + g;
        #pragma unroll
        for (int nt = 0; nt < 4; nt++) {
            int gn = bn + wn * 32 + nt * 8 + tg * 2;
            float b0v = sg.bias ? sg.bias[gn]     : 0.f;
            float b1v = sg.bias ? sg.bias[gn + 1] : 0.f;
            float x0 = acc[mt][nt][0] + b0v, x1 = acc[mt][nt][1] + b1v;
            float x2 = acc[mt][nt][2] + b0v, x3 = acc[mt][nt][3] + b1v;
            if (sg.act == 1) { x0 = gelu_exact(x0); x1 = gelu_exact(x1); x2 = gelu_exact(x2); x3 = gelu_exact(x3); }
            else if (sg.act == 2) { x0 = sigmoidf(x0); x1 = sigmoidf(x1); x2 = sigmoidf(x2); x3 = sigmoidf(x3); }
            if (sg.cb) {
                unsigned* Cb = (unsigned*)sg.C;
                Cb[(size_t)gm * KP + (gn >> 1)]       = packbf(x0, x1);
                Cb[(size_t)(gm + 8) * KP + (gn >> 1)] = packbf(x2, x3);
            } else {
                float* C = (float*)sg.C;
                *(float2*)&C[(size_t)gm * DD + gn]       = make_float2(x0, x1);
                *(float2*)&C[(size_t)(gm + 8) * DD + gn] = make_float2(x2, x3);
            }
        }
    }
}

// ================= tf32 batched QK^T per (b,h) — round-10 exact =================
#define QK_SMEM (2 * 128 * 68 * 4)
template<int MODE>
__global__ __launch_bounds__(256, 2) void qk_t(
    const float* __restrict__ qb, const float* __restrict__ kb, long kbStride,
    const float* __restrict__ bd, const float* __restrict__ tu, const float* __restrict__ tv,
    float* __restrict__ outp)
{
    extern __shared__ unsigned sh[];
    unsigned (*As)[68] = (unsigned(*)[68])sh;
    unsigned (*Bs)[68] = (unsigned(*)[68])(sh + 128 * 68);
    const int bh = blockIdx.z, b = bh >> 4, h = bh & 15;
    const float* Aq = qb + (size_t)b * SS * DD + h * DH;
    const float* Bk = kb + (size_t)b * kbStride + h * DH;
    const int bs0 = blockIdx.y * 128, bf0 = blockIdx.x * 128;
    const int t = threadIdx.x, lane = t & 31, wid = t >> 5;
    const int wm = wid >> 2, wn = wid & 3;
    const int g = lane >> 2, tg = lane & 3;
    const int lr = t >> 2, q4 = t & 3;

    if (MODE == 0) {
        if (bf0 + 127 < (SS - 128) - bs0) return;
    } else {
        if (bf0 > bs0 + 127 + MM) {
            #pragma unroll
            for (int mt = 0; mt < 4; mt++) {
                int s0g = bs0 + wm * 64 + mt * 16 + g;
                #pragma unroll
                for (int nt = 0; nt < 4; nt++) {
                    int f0g = bf0 + wn * 32 + nt * 8 + tg * 2;
                    #pragma unroll
                    for (int half = 0; half < 2; half++) {
                        size_t rowoff = ((size_t)bh * SS + s0g + half * 8) * FF;
                        *(float2*)&outp[rowoff + f0g] = make_float2(-1e30f, -1e30f);
                    }
                }
            }
            return;
        }
    }

    #pragma unroll
    for (int j = 0; j < 4; j++) {
        int c = (q4 + 4 * j) * 4;
        cpa16(&As[lr][c],      Aq + (size_t)(bs0 + lr) * DD + c);
        cpa16(&As[lr + 64][c], Aq + (size_t)(bs0 + lr + 64) * DD + c);
        cpa16(&Bs[lr][c],      Bk + (size_t)(bf0 + lr) * DD + c);
        cpa16(&Bs[lr + 64][c], Bk + (size_t)(bf0 + lr + 64) * DD + c);
    }
    cpa_commit();

    float acc[4][4][4];
    #pragma unroll
    for (int i = 0; i < 4; i++)
        #pragma unroll
        for (int j = 0; j < 4; j++)
            #pragma unroll
            for (int r = 0; r < 4; r++) acc[i][j][r] = 0.f;

    cpa_wait<0>();
    __syncthreads();

    #pragma unroll
    for (int kk = 0; kk < 64; kk += 8) {
        unsigned af[4][4], bf[4][2];
        #pragma unroll
        for (int mt = 0; mt < 4; mt++) {
            int r = wm * 64 + mt * 16 + g;
            af[mt][0] = As[r][kk + tg];
            af[mt][1] = As[r + 8][kk + tg];
            af[mt][2] = As[r][kk + tg + 4];
            af[mt][3] = As[r + 8][kk + tg + 4];
        }
        #pragma unroll
        for (int nt = 0; nt < 4; nt++) {
            int c = wn * 32 + nt * 8 + g;
            bf[nt][0] = rna(Bs[c][kk + tg]);
            bf[nt][1] = rna(Bs[c][kk + tg + 4]);
        }
        #pragma unroll
        for (int mt = 0; mt < 4; mt++)
            #pragma unroll
            for (int nt = 0; nt < 4; nt++)
                mma8(acc[mt][nt], af[mt], bf[nt]);
    }

    #pragma unroll
    for (int mt = 0; mt < 4; mt++) {
        int s0g = bs0 + wm * 64 + mt * 16 + g;
        #pragma unroll
        for (int nt = 0; nt < 4; nt++) {
            int f0g = bf0 + wn * 32 + nt * 8 + tg * 2;
            #pragma unroll
            for (int half = 0; half < 2; half++) {
                int s_g = s0g + half * 8;
                float y0 = acc[mt][nt][half * 2 + 0];
                float y1 = acc[mt][nt][half * 2 + 1];
                size_t rowoff = ((size_t)bh * SS + s_g) * FF;
                if (MODE == 0) {
                    *(float2*)&outp[rowoff + f0g] = make_float2(y0, y1);
                } else {
                    const float* bdrow = bd + rowoff;
                    const float* tvrow = tv + (size_t)h * FF;
                    const float* turow = tu + (size_t)bh * FF;
                    float v0, v1;
                    int fp0 = f0g + (SS - 1) - s_g;
                    if (f0g > s_g + MM) v0 = -1e30f;
                    else v0 = (y0 + turow[f0g] + bdrow[fp0] + tvrow[fp0]) * 0.03125f;
                    if (f0g + 1 > s_g + MM) v1 = -1e30f;
                    else v1 = (y1 + turow[f0g + 1] + bdrow[fp0 + 1] + tvrow[fp0 + 1]) * 0.03125f;
                    *(float2*)&outp[rowoff + f0g] = make_float2(v0, v1);
                }
            }
        }
    }
}

// ---------------- softmax per row + loss max — round-10 exact ----------------
__global__ __launch_bounds__(256) void softmax_k(
    const float* __restrict__ sc, float* __restrict__ attn,
    unsigned* __restrict__ abf, float* __restrict__ bhmax)
{
    size_t row = blockIdx.x;
    int bh = (int)(row / SS);
    const float4* src = (const float4*)(sc + row * FF);
    float4* dst = (float4*)(attn + row * FF);
    uint2* dstb = (uint2*)(abf + row * (FF / 2));
    int t = threadIdx.x;
    float4 v0 = src[t], v1 = src[t + 256];
    float m = fmaxf(fmaxf(fmaxf(v0.x, v0.y), fmaxf(v0.z, v0.w)),
                    fmaxf(fmaxf(v1.x, v1.y), fmaxf(v1.z, v1.w)));
    #pragma unroll
    for (int o = 16; o; o >>= 1) m = fmaxf(m, __shfl_xor_sync(0xffffffffu, m, o));
    __shared__ float red[8];
    int w = t >> 5, l = t & 31;
    if (l == 0) red[w] = m;
    __syncthreads();
    float mAll = red[0];
    #pragma unroll
    for (int i = 1; i < 8; i++) mAll = fmaxf(mAll, red[i]);
    __syncthreads();

    float e0x = fexp(v0.x - mAll), e0y = fexp(v0.y - mAll);
    float e0z = fexp(v0.z - mAll), e0w = fexp(v0.w - mAll);
    float e1x = fexp(v1.x - mAll), e1y = fexp(v1.y - mAll);
    float e1z = fexp(v1.z - mAll), e1w = fexp(v1.w - mAll);
    float s = e0x + e0y + e0z + e0w + e1x + e1y + e1z + e1w;
    #pragma unroll
    for (int o = 16; o; o >>= 1) s += __shfl_xor_sync(0xffffffffu, s, o);
    if (l == 0) red[w] = s;
    __syncthreads();
    float sAll = 0.f;
    #pragma unroll
    for (int i = 0; i < 8; i++) sAll += red[i];
    float inv = 1.0f / sAll;
    float a0 = e0x * inv, a1 = e0y * inv, a2 = e0z * inv, a3 = e0w * inv;
    float b0 = e1x * inv, b1 = e1y * inv, b2 = e1z * inv, b3 = e1w * inv;
    dst[t]       = make_float4(a0, a1, a2, a3);
    dst[t + 256] = make_float4(b0, b1, b2, b3);
    dstb[t]       = make_uint2(packbf(a0, a1), packbf(a2, a3));
    dstb[t + 256] = make_uint2(packbf(b0, b1), packbf(b2, b3));
    if (t == 0) atomicMax((int*)(bhmax + bh), __float_as_int(inv));
}

// ---------------- v transpose to packed bf16: vt[bh][d][f/2] ----------------
__global__ __launch_bounds__(256) void vtrans_k(
    const float* __restrict__ v, unsigned* __restrict__ vt)
{
    int bh = blockIdx.y, b = bh >> 4, h = bh & 15;
    int f0 = blockIdx.x * 128;
    __shared__ float vs[128][65];
    const float* src = v + (size_t)b * FF * DD + (size_t)f0 * DD + h * DH;
    int t = threadIdx.x;
    #pragma unroll
    for (int j = 0; j < 8; j++) {
        int idx = t + j * 256;
        int row = idx >> 4, c4 = (idx & 15) * 4;
        float4 x = *(const float4*)(src + (size_t)row * DD + c4);
        vs[row][c4] = x.x; vs[row][c4 + 1] = x.y; vs[row][c4 + 2] = x.z; vs[row][c4 + 3] = x.w;
    }
    __syncthreads();
    unsigned* dstb = vt + (size_t)bh * DH * (FF / 2) + f0 / 2;
    #pragma unroll
    for (int j = 0; j < 16; j++) {
        int idx = t + j * 256;
        int d = idx >> 6, fp = idx & 63;
        dstb[(size_t)d * (FF / 2) + fp] = packbf(vs[2 * fp][d], vs[2 * fp + 1][d]);
    }
}

// ================= bf16 attn @ v per (b,h): writes packed bf16 ao (3-stage) =================
__global__ __launch_bounds__(256, 2) void av_b(
    const unsigned* __restrict__ abf, const unsigned* __restrict__ vt, unsigned* __restrict__ aob)
{
    const int bh = blockIdx.y, b = bh >> 4, h = bh & 15;
    const int bs0 = blockIdx.x * 128;
    __shared__ unsigned As[GST][128][20];
    __shared__ unsigned Vs[GST][64][20];
    const int t = threadIdx.x, lane = t & 31, wid = t >> 5;
    const int wm = wid >> 1, wn = wid & 1;
    const int g = lane >> 2, tg = lane & 3;

    const int ar = t >> 1, ac = (t & 1) * 8;
    const int vr = t >> 2, vc = (t & 3) * 4;

    const unsigned* Ap = abf + ((size_t)bh * SS + bs0 + ar) * (FF / 2);
    const unsigned* Vp = vt + ((size_t)bh * DH + vr) * (FF / 2);

    const int nit = min(FF / 32, (bs0 + 1183) >> 5);

    float acc[2][4][4];
    #pragma unroll
    for (int i = 0; i < 2; i++)
        #pragma unroll
        for (int j = 0; j < 4; j++)
            #pragma unroll
            for (int r = 0; r < 4; r++) acc[i][j][r] = 0.f;

    #pragma unroll 1
    for (int s = 0; s < GST - 1; s++) {
        long o = (long)s * 16;
        cpa16(&As[s][ar][ac],     Ap + o + ac);
        cpa16(&As[s][ar][ac + 4], Ap + o + ac + 4);
        cpa16(&Vs[s][vr][vc],     Vp + o + vc);
        cpa_commit();
    }

    for (int it = 0; it < nit; ++it) {
        cpa_wait<GST - 2>();
        __syncthreads();
        if (it + GST - 1 < nit) {
            int st = (it + GST - 1) % GST;
            long o = (long)(it + GST - 1) * 16;
            cpa16(&As[st][ar][ac],     Ap + o + ac);
            cpa16(&As[st][ar][ac + 4], Ap + o + ac + 4);
            cpa16(&Vs[st][vr][vc],     Vp + o + vc);
            cpa_commit();
        }
        const int cur = it % GST;
        #pragma unroll
        for (int kkp = 0; kkp < 16; kkp += 8) {
            unsigned af[2][4], bf[4][2];
            #pragma unroll
            for (int mt = 0; mt < 2; mt++) {
                int r = wm * 32 + mt * 16 + g;
                af[mt][0] = As[cur][r][kkp + tg];
                af[mt][1] = As[cur][r + 8][kkp + tg];
                af[mt][2] = As[cur][r][kkp + tg + 4];
                af[mt][3] = As[cur][r + 8][kkp + tg + 4];
            }
            #pragma unroll
            for (int nt = 0; nt < 4; nt++) {
                int d = wn * 32 + nt * 8 + g;
                bf[nt][0] = Vs[cur][d][kkp + tg];
                bf[nt][1] = Vs[cur][d][kkp + tg + 4];
            }
            #pragma unroll
            for (int mt = 0; mt < 2; mt++)
                #pragma unroll
                for (int nt = 0; nt < 4; nt++)
                    mma16(acc[mt][nt], af[mt], bf[nt]);
        }
    }

    #pragma unroll
    for (int mt = 0; mt < 2; mt++) {
        int gm = bs0 + wm * 32 + mt * 16 + g;
        #pragma unroll
        for (int nt = 0; nt < 4; nt++) {
            int gn = wn * 32 + nt * 8 + tg * 2;
            int col = h * (DH / 2) + (gn >> 1);
            aob[((size_t)b * SS + gm) * KP + col]     = packbf(acc[mt][nt][0], acc[mt][nt][1]);
            aob[((size_t)b * SS + gm + 8) * KP + col] = packbf(acc[mt][nt][2], acc[mt][nt][3]);
        }
    }
}

__global__ void zero32_k(float* p) { if (threadIdx.x < Bb * HH) p[threadIdx.x] = 0.f; }

__global__ void loss_k(const float* __restrict__ bhm, float* __restrict__ out)
{
    int t = threadIdx.x;
    float v = (t < Bb * HH) ? bhm[t] : 0.f;
    #pragma unroll
    for (int o = 16; o; o >>= 1) v += __shfl_xor_sync(0xffffffffu, v, o);
    if (t == 0) out[0] = v * (1.0f / (Bb * HH));
}

// ---------------- launch ----------------
extern "C" void kernel_launch(void* const* d_in, const int* in_sizes, int n_in,
                              void* d_out, int out_size)
{
    const float* inputs = (const float*)d_in[0];
    const float* mem    = (const float*)d_in[1];
    const float* c2     = (const float*)d_in[2];
    const float* c3     = (const float*)d_in[3];
    const float* ln1g   = (const float*)d_in[4];
    const float* ln1b   = (const float*)d_in[5];
    const float* wq     = (const float*)d_in[6];
    const float* wke    = (const float*)d_in[7];
    const float* wkr    = (const float*)d_in[8];
    const float* wv     = (const float*)d_in[9];
    const float* wf     = (const float*)d_in[10];
    const float* up     = (const float*)d_in[11];
    const float* vp     = (const float*)d_in[12];
    const float* ln2g   = (const float*)d_in[13];
    const float* ln2b   = (const float*)d_in[14];
    const float* w1     = (const float*)d_in[15];
    const float* b1     = (const float*)d_in[16];
    const float* w2     = (const float*)d_in[17];
    const float* b2     = (const float*)d_in[18];
    const float* wg1    = (const float*)d_in[19];
    const float* bg1    = (const float*)d_in[20];
    const float* wg2    = (const float*)d_in[21];
    const float* bg2    = (const float*)d_in[22];
    float* out = (float*)d_out;

    float *xt, *q, *k, *v, *rel, *Qr, *bd, *sc, *sg, *g1, *tu, *tv, *wr, *bhm;
    unsigned *wtb, *abf, *vt, *aob, *ibf, *g1b, *h0b, *h1b;
    cudaGetSymbolAddress((void**)&xt,  g_xt);
    cudaGetSymbolAddress((void**)&q,   g_q);
    cudaGetSymbolAddress((void**)&k,   g_k);
    cudaGetSymbolAddress((void**)&v,   g_v);
    cudaGetSymbolAddress((void**)&rel, g_rel);
    cudaGetSymbolAddress((void**)&Qr,  g_Qr);
    cudaGetSymbolAddress((void**)&bd,  g_bd);
    cudaGetSymbolAddress((void**)&sc,  g_sc);
    cudaGetSymbolAddress((void**)&sg,  g_sg);
    cudaGetSymbolAddress((void**)&g1,  g_g1);
    cudaGetSymbolAddress((void**)&tu,  g_tu);
    cudaGetSymbolAddress((void**)&tv,  g_tv);
    cudaGetSymbolAddress((void**)&wr,  g_wr);
    cudaGetSymbolAddress((void**)&wtb, g_wtb);
    cudaGetSymbolAddress((void**)&abf, g_abf);
    cudaGetSymbolAddress((void**)&vt,  g_vt);
    cudaGetSymbolAddress((void**)&aob, g_aob);
    cudaGetSymbolAddress((void**)&ibf, g_ibf);
    cudaGetSymbolAddress((void**)&g1b, g_g1b);
    cudaGetSymbolAddress((void**)&h0b, g_h0b);
    cudaGetSymbolAddress((void**)&h1b, g_h1b);
    cudaGetSymbolAddress((void**)&bhm, g_bhmax);

    static bool init = false;
    static cudaStream_t st1, st2, st3;
    static cudaEvent_t eRoot, eW4, eRel, eT4, eVT, ePD, eG1;
    if (!init) {
        cudaFuncSetAttribute(gemm_t4,     cudaFuncAttributeMaxDynamicSharedMemorySize, GEMM_SMEM);
        cudaFuncSetAttribute(gemm_b2,     cudaFuncAttributeMaxDynamicSharedMemorySize, GB_SMEM);
        cudaFuncSetAttribute(gemm_bf<0>,  cudaFuncAttributeMaxDynamicSharedMemorySize, GB_SMEM);
        cudaFuncSetAttribute(gemm_bf<1>,  cudaFuncAttributeMaxDynamicSharedMemorySize, GB_SMEM);
        cudaFuncSetAttribute(gemm_bf<2>,  cudaFuncAttributeMaxDynamicSharedMemorySize, GB_SMEM);
        cudaFuncSetAttribute(qk_t<0>,     cudaFuncAttributeMaxDynamicSharedMemorySize, QK_SMEM);
        cudaFuncSetAttribute(qk_t<1>,     cudaFuncAttributeMaxDynamicSharedMemorySize, QK_SMEM);
        cudaStreamCreateWithFlags(&st1, cudaStreamNonBlocking);
        cudaStreamCreateWithFlags(&st2, cudaStreamNonBlocking);
        cudaStreamCreateWithFlags(&st3, cudaStreamNonBlocking);
        cudaEventCreateWithFlags(&eRoot, cudaEventDisableTiming);
        cudaEventCreateWithFlags(&eW4,   cudaEventDisableTiming);
        cudaEventCreateWithFlags(&eRel,  cudaEventDisableTiming);
        cudaEventCreateWithFlags(&eT4,   cudaEventDisableTiming);
        cudaEventCreateWithFlags(&eVT,   cudaEventDisableTiming);
        cudaEventCreateWithFlags(&ePD,   cudaEventDisableTiming);
        cudaEventCreateWithFlags(&eG1,   cudaEventDisableTiming);
        init = true;
    }

    const long OUT_N  = (long)Bb * SS * DD;
    const long ATTN_N = (long)Bb * HH * SS * FF;
    bool has_attn = ((long)out_size >= OUT_N + ATTN_N);
    bool has_loss = ((long)out_size >= OUT_N + ATTN_N + 1);
    float* attn = has_attn ? (out + OUT_N) : bd;

    const long WN = (long)DD * DD;
    float* rwq  = wr + 0 * WN; float* rwke = wr + 1 * WN;
    float* rwkr = wr + 2 * WN; float* rwv  = wr + 3 * WN;
    unsigned* twf  = wtb + 0 * DD * KP; unsigned* tw1  = wtb + 1 * DD * KP;
    unsigned* tw2  = wtb + 2 * DD * KP; unsigned* twg1 = wtb + 3 * DD * KP;
    unsigned* twg2 = wtb + 4 * DD * KP;

    // ---- fork root ----
    zero32_k<<<1, 32>>>(bhm);
    cudaEventRecord(eRoot, 0);

    // ---- st1 (forked): attention-weight prep ----
    cudaStreamWaitEvent(st1, eRoot, 0);
    {
        Ptr4 p4; p4.p[0] = wq; p4.p[1] = wke; p4.p[2] = wkr; p4.p[3] = wv;
        dim3 g((int)(WN / 4 / 256), 4);
        wround4_k<<<g, 256, 0, st1>>>(p4, wr);
        cudaEventRecord(eW4, st1);
    }

    // ---- st2 (forked): FFN weight prep + ibf + gate1 GEMM ----
    cudaStreamWaitEvent(st2, eRoot, 0);
    {
        Ptr5 p5; p5.p[0] = wf; p5.p[1] = w1; p5.p[2] = w2; p5.p[3] = wg1; p5.p[4] = wg2;
        dim3 g(128, 5);
        wtrans5_k<<<g, 256, 0, st2>>>(p5, wtb);
        int n = Bb * SS * KP;
        tobf_k<<<(n + 255) / 256, 256, 0, st2>>>((const float2*)inputs, ibf, n);
        dim3 gb(DD / 128, (Bb * SS) / 128);
        gemm_bf<0><<<gb, 256, GB_SMEM, st2>>>(ibf, twg1, bg1, nullptr, nullptr, sg, nullptr);
        cudaEventRecord(eG1, st2);
    }

    // ---- st3 (forked): rel pick ----
    cudaStreamWaitEvent(st3, eRoot, 0);
    {
        const int n4 = (FF * DD) / 4;
        pick_rel_k<<<(n4 + 255) / 256, 256, 0, st3>>>(c2, c3, rel);
        cudaEventRecord(eRel, st3);
    }

    // ---- s0: LN1 (overlaps the forks) ----
    ln_concat_k<<<Bb * FF, 256>>>(inputs, mem, ln1g, ln1b, xt);

    // ---- s0: fused q/k/v/Qr ----
    cudaStreamWaitEvent(0, eW4, 0);
    cudaStreamWaitEvent(0, eRel, 0);
    {
        T4 p;
        p.xt = xt; p.rel = rel;
        p.wq = rwq; p.wke = rwke; p.wv = rwv; p.wkr = rwkr;
        p.q = q; p.k = k; p.v = v; p.Qr = Qr;
        dim3 g(DD / 128, 96);
        gemm_t4<<<g, 256, GEMM_SMEM>>>(p);
        cudaEventRecord(eT4, 0);
    }

    // ---- st1 (refork): vtrans ----
    cudaStreamWaitEvent(st1, eT4, 0);
    {
        dim3 g(FF / 128, Bb * HH);
        vtrans_k<<<g, 256, 0, st1>>>(v, vt);
        cudaEventRecord(eVT, st1);
    }
    // ---- st3 (refork): pdot tu/tv ----
    cudaStreamWaitEvent(st3, eT4, 0);
    {
        dim3 gtu(FF / 8, Bb * HH), gtv(FF / 8, HH);
        pdot_k<<<gtu, 256, 0, st3>>>(up, k, (long)FF * DD, 1, tu);
        pdot_k<<<gtv, 256, 0, st3>>>(vp, Qr, 0, 0, tv);
        cudaEventRecord(ePD, st3);
    }

    // ---- s0: qk0 / qk1 / softmax / av ----
    {
        dim3 g(FF / 128, SS / 128, Bb * HH);
        qk_t<0><<<g, 256, QK_SMEM>>>(q, Qr, 0L, nullptr, nullptr, nullptr, bd);
    }
    cudaStreamWaitEvent(0, ePD, 0);
    {
        dim3 g(FF / 128, SS / 128, Bb * HH);
        qk_t<1><<<g, 256, QK_SMEM>>>(q, k, (long)FF * DD, bd, tu, tv, sc);
    }

    softmax_k<<<Bb * HH * SS, 256>>>(sc, attn, abf, bhm);

    cudaStreamWaitEvent(0, eVT, 0);
    {
        dim3 g(SS / 128, Bb * HH);
        av_b<<<g, 256>>>(abf, vt, aob);
    }

    // ---- s0: FFN tail with fused epilogues ----
    cudaStreamWaitEvent(0, eG1, 0);
    dim3 gb(DD / 128, (Bb * SS) / 128);
    // g1 = inputs + sg * gelu(ao@wf); writes g1 fp32 + g1b bf16
    gemm_bf<1><<<gb, 256, GB_SMEM>>>(aob, twf, nullptr, inputs, sg, g1, g1b);
    ln_bf_k<<<Bb * SS, 256>>>(g1, ln2g, ln2b, h0b);
    {
        B2 p;
        p.s0.A = h0b; p.s0.Wt = tw1;  p.s0.bias = b1;  p.s0.C = h1b; p.s0.act = 1; p.s0.cb = 1;
        p.s1.A = g1b; p.s1.Wt = twg2; p.s1.bias = bg2; p.s1.C = sg;  p.s1.act = 2; p.s1.cb = 0;
        dim3 g(DD / 128, 32);
        gemm_b2<<<g, 256, GB_SMEM>>>(p);
    }
    // out = g1 + sg * gelu(h1@w2 + b2)
    gemm_bf<2><<<gb, 256, GB_SMEM>>>(h1b, tw2, b2, g1, sg, out, nullptr);

    if (has_loss) loss_k<<<1, 32>>>(bhm, out + OUT_N + ATTN_N);
}